// round 7
// baseline (speedup 1.0000x reference)
#include <cuda_runtime.h>
#include <cuda_bf16.h>
#include <math.h>

// Problem constants
// B=2, N=2048, H=256, heads=8, d=32, WIN=32, WIN_LEN=65
#define BB 2
#define NN 2048
#define HH 256
#define NH 8
#define HD 32
#define WIN 32
#define WLEN 65
#define BHN (BB*NH)         // 16
#define BN (BB*NN)          // 4096

// ---------------- scratch (device globals; no allocation allowed) -------------
__device__ float g_q[BHN*NN*HD];        // (bh, n, d)
__device__ float g_k[BHN*NN*HD];
__device__ float g_v[BHN*NN*HD];
__device__ float g_vp[BN*3*512];        // vec_proj (bn*3+c, 512)
__device__ float g_vd[BN*HH];           // vec_dot (bn, j)
__device__ float g_vn[BN*HH];           // vec_norm
__device__ float g_xout[BN*HH];         // x_out (bn, H)
__device__ float g_vaggr[BN*3*HH];      // (bn, c, H)
__device__ float g_gate[BN*HH];

// ======================= SGEMM: QKV (M=4096, N=256, K=256) ====================
// 128x64 tile, 8x4 microtile, 256 threads. z selects Wq/Wk/Wv. Scatter epilogue.
__global__ __launch_bounds__(256) void gemm_qkv_kernel(
    const float* __restrict__ x,
    const float* __restrict__ Wq, const float* __restrict__ Wk, const float* __restrict__ Wv,
    const float* __restrict__ bq, const float* __restrict__ bk, const float* __restrict__ bv)
{
    __shared__ float As[128][17];
    __shared__ float Bs[16][64];
    int z = blockIdx.z;
    const float* W    = (z==0) ? Wq : (z==1 ? Wk : Wv);
    const float* bias = (z==0) ? bq : (z==1 ? bk : bv);
    float* dst        = (z==0) ? g_q : (z==1 ? g_k : g_v);

    int m0 = blockIdx.x*128, n0 = blockIdx.y*64;
    int tid = threadIdx.x;
    int tx = tid & 15, ty = tid >> 4;           // ty: 0..15 -> 8 rows each
    int la_m = tid >> 1, la_k = (tid & 1) << 3; // 128 rows, 8 k each
    int lb_k = tid >> 4, lb_n = (tid & 15) << 2;

    float acc[8][4];
#pragma unroll
    for (int i=0;i<8;i++)
#pragma unroll
        for (int j=0;j<4;j++) acc[i][j]=0.f;

    const float* arow = x + (size_t)(m0+la_m)*1024;

    for (int k0=0;k0<256;k0+=16) {
        float4 a0 = *(const float4*)(arow + k0 + la_k);
        float4 a1 = *(const float4*)(arow + k0 + la_k + 4);
        As[la_m][la_k+0]=a0.x; As[la_m][la_k+1]=a0.y; As[la_m][la_k+2]=a0.z; As[la_m][la_k+3]=a0.w;
        As[la_m][la_k+4]=a1.x; As[la_m][la_k+5]=a1.y; As[la_m][la_k+6]=a1.z; As[la_m][la_k+7]=a1.w;
        float4 bv4 = *(const float4*)(W + (size_t)(k0+lb_k)*256 + n0 + lb_n);
        *(float4*)&Bs[lb_k][lb_n] = bv4;
        __syncthreads();
#pragma unroll
        for (int kk=0;kk<16;kk++) {
            float a[8];
#pragma unroll
            for (int i=0;i<8;i++) a[i] = As[ty*8+i][kk];
            float4 b = *(const float4*)&Bs[kk][tx*4];
#pragma unroll
            for (int i=0;i<8;i++) {
                acc[i][0]+=a[i]*b.x; acc[i][1]+=a[i]*b.y;
                acc[i][2]+=a[i]*b.z; acc[i][3]+=a[i]*b.w;
            }
        }
        __syncthreads();
    }
#pragma unroll
    for (int i=0;i<8;i++) {
        int m = m0 + ty*8 + i;
        int b = m >> 11, n = m & 2047;
#pragma unroll
        for (int j=0;j<4;j++) {
            int col = n0 + tx*4 + j;
            int h = col >> 5, dd = col & 31;
            dst[(((size_t)(b*NH + h))*NN + n)*HD + dd] = acc[i][j] + bias[col];
        }
    }
}

// ================= SGEMM: vec_proj (M=12288, N=512, K=256) ====================
__global__ __launch_bounds__(256) void gemm_vp_kernel(
    const float* __restrict__ x, const float* __restrict__ Wvec)
{
    __shared__ float As[128][17];
    __shared__ float Bs[16][64];
    int m0 = blockIdx.x*128, n0 = blockIdx.y*64;
    int tid = threadIdx.x;
    int tx = tid & 15, ty = tid >> 4;
    int la_m = tid >> 1, la_k = (tid & 1) << 3;
    int lb_k = tid >> 4, lb_n = (tid & 15) << 2;

    float acc[8][4];
#pragma unroll
    for (int i=0;i<8;i++)
#pragma unroll
        for (int j=0;j<4;j++) acc[i][j]=0.f;

    int m = m0 + la_m;
    const float* arow = x + ((size_t)(m/3)*4 + 1 + (m%3))*256;

    for (int k0=0;k0<256;k0+=16) {
        float4 a0 = *(const float4*)(arow + k0 + la_k);
        float4 a1 = *(const float4*)(arow + k0 + la_k + 4);
        As[la_m][la_k+0]=a0.x; As[la_m][la_k+1]=a0.y; As[la_m][la_k+2]=a0.z; As[la_m][la_k+3]=a0.w;
        As[la_m][la_k+4]=a1.x; As[la_m][la_k+5]=a1.y; As[la_m][la_k+6]=a1.z; As[la_m][la_k+7]=a1.w;
        float4 bv4 = *(const float4*)(Wvec + (size_t)(k0+lb_k)*512 + n0 + lb_n);
        *(float4*)&Bs[lb_k][lb_n] = bv4;
        __syncthreads();
#pragma unroll
        for (int kk=0;kk<16;kk++) {
            float a[8];
#pragma unroll
            for (int i=0;i<8;i++) a[i] = As[ty*8+i][kk];
            float4 b = *(const float4*)&Bs[kk][tx*4];
#pragma unroll
            for (int i=0;i<8;i++) {
                acc[i][0]+=a[i]*b.x; acc[i][1]+=a[i]*b.y;
                acc[i][2]+=a[i]*b.z; acc[i][3]+=a[i]*b.w;
            }
        }
        __syncthreads();
    }
#pragma unroll
    for (int i=0;i<8;i++) {
        int mm = m0 + ty*8 + i;
#pragma unroll
        for (int j=0;j<4;j++) {
            int col = n0 + tx*4 + j;
            g_vp[(size_t)mm*512 + col] = acc[i][j];
        }
    }
}

// ============== elementwise: vec_dot and vec_norm (per bn, j) =================
__global__ void vecdot_norm_kernel(const float* __restrict__ x)
{
    int bn = blockIdx.x, j = threadIdx.x;
    float vd = 0.f, s = 0.f;
#pragma unroll
    for (int c=0;c<3;c++) {
        float a  = g_vp[((size_t)bn*3 + c)*512 + j];
        float b2 = g_vp[((size_t)bn*3 + c)*512 + 256 + j];
        vd += a*b2;
        float xv = x[((size_t)bn*4 + 1 + c)*256 + j];
        s += xv*xv;
    }
    g_vd[(size_t)bn*256 + j] = vd;
    g_vn[(size_t)bn*256 + j] = sqrtf(s);
}

// ===================== sliding-window attention ===============================
// Block: (t, bh). TQ=64 queries, 256 threads (4 per query). 128 staged rows.
// Smem ~105KB -> 2 CTAs/SM, 16 warps/SM.
#define TQ 64
#define ROWS 128
#define KSTR 36
#define VSTR 100
#define WSTR 67
__global__ __launch_bounds__(256) void attn_kernel(
    const float* __restrict__ x, float* __restrict__ attn_out)
{
    extern __shared__ float sm[];
    float* ks   = sm;                    // 128*36 = 4608
    float* vs   = ks + ROWS*KSTR;        // 4608
    float* vecs = vs + ROWS*KSTR;        // 128*100 = 12800
    float* wts  = vecs + ROWS*VSTR;      // 64*67   = 4288

    int t  = blockIdx.x;
    int bh = blockIdx.y;
    int b = bh >> 3, h = bh & 7;
    int n_base = t*TQ;
    int tid = threadIdx.x;

    // stage k, v  (128 rows x 32)
    for (int idx = tid; idx < ROWS*32; idx += 256) {
        int r = idx >> 5, d = idx & 31;
        int ng = n_base - WIN + r;
        float kv = 0.f, vv = 0.f;
        if (ng >= 0 && ng < NN) {
            size_t o = ((size_t)bh*NN + ng)*HD + d;
            kv = g_k[o]; vv = g_v[o];
        }
        ks[r*KSTR + d] = kv;
        vs[r*KSTR + d] = vv;
    }
    // stage vec windows (3 components of this head)
    for (int idx = tid; idx < ROWS*96; idx += 256) {
        int r = idx / 96, jj = idx - r*96;
        int c = jj >> 5, dd = jj & 31;
        int ng = n_base - WIN + r;
        float vv = 0.f;
        if (ng >= 0 && ng < NN)
            vv = x[(((size_t)b*NN + ng)*4 + 1 + c)*256 + h*HD + dd];
        vecs[r*VSTR + jj] = vv;
    }
    __syncthreads();

    int qi = tid >> 2;        // 0..63
    int p  = tid & 3;         // 0..3
    int n  = n_base + qi;

    // ---------------- scores: thread p does w = p, p+4, ... ----------------
    {
        float4 q[8];
        const float4* qp = (const float4*)(g_q + ((size_t)bh*NN + n)*HD);
#pragma unroll
        for (int i=0;i<8;i++) q[i] = qp[i];

        const float scale = 0.17677669529663687f;  // 1/sqrt(32)

        float mx = -1e30f;
        for (int w=p; w<WLEN; w+=4) {
            const float4* kr = (const float4*)(ks + (qi+w)*KSTR);
            float s = 0.f;
#pragma unroll
            for (int i=0;i<8;i++) {
                float4 kv = kr[i];
                s += q[i].x*kv.x + q[i].y*kv.y + q[i].z*kv.z + q[i].w*kv.w;
            }
            s *= scale;
            wts[qi*WSTR + w] = s;
            mx = fmaxf(mx, s);
        }
        mx = fmaxf(mx, __shfl_xor_sync(0xffffffffu, mx, 1));
        mx = fmaxf(mx, __shfl_xor_sync(0xffffffffu, mx, 2));
        float sum = 0.f;
        for (int w=p; w<WLEN; w+=4) {
            float e = __expf(wts[qi*WSTR + w] - mx);
            wts[qi*WSTR + w] = e;
            sum += e;
        }
        sum += __shfl_xor_sync(0xffffffffu, sum, 1);
        sum += __shfl_xor_sync(0xffffffffu, sum, 2);
        float inv = 1.f/sum;
        for (int w=p; w<WLEN; w+=4) wts[qi*WSTR + w] *= inv;
    }
    __syncwarp();   // 4-lane group of each query is within one warp

    // ---------------- aggregation: thread p does pass p --------------------
    // p==0: v (32 dims) -> g_xout ; p==1..3: vec channel p-1 -> g_vaggr
    {
        float4 acc[8];
#pragma unroll
        for (int i=0;i<8;i++) acc[i] = make_float4(0.f,0.f,0.f,0.f);

        const float* base = (p==0) ? vs : (vecs + (p-1)*32);
        int stride = (p==0) ? KSTR : VSTR;

        for (int w=0; w<WLEN; w++) {
            float wv = wts[qi*WSTR + w];          // broadcast across 4 lanes
            const float4* vr = (const float4*)(base + (qi+w)*stride);
#pragma unroll
            for (int i=0;i<8;i++) {
                float4 v = vr[i];
                acc[i].x += wv*v.x; acc[i].y += wv*v.y;
                acc[i].z += wv*v.z; acc[i].w += wv*v.w;
            }
        }
        float4* outp;
        if (p==0) outp = (float4*)(g_xout + ((size_t)b*NN + n)*HH + h*HD);
        else      outp = (float4*)(g_vaggr + (((size_t)b*NN + n)*3 + (p-1))*HH + h*HD);
#pragma unroll
        for (int i=0;i<8;i++) outp[i] = acc[i];
    }
    __syncthreads();

    // coalesced write of attention weights: (bh, n, w) contiguous over tile
    {
        float* ao = attn_out + ((size_t)bh*NN + n_base)*WLEN;
        for (int idx = tid; idx < TQ*WLEN; idx += 256) {
            int q2 = idx / WLEN, w = idx - q2*WLEN;
            ao[idx] = wts[q2*WSTR + w];
        }
    }
}

// =============== SGEMM: gate (M=4096, N=256, K=512, sigmoid) ==================
__global__ __launch_bounds__(256) void gemm_gate_kernel(
    const float* __restrict__ p_ad, const float* __restrict__ p_an,
    const float* __restrict__ Wg, const float* __restrict__ bg)
{
    __shared__ float As[128][17];
    __shared__ float Bs[16][64];
    float ad = *p_ad, an = *p_an;
    int m0 = blockIdx.x*128, n0 = blockIdx.y*64;
    int tid = threadIdx.x;
    int tx = tid & 15, ty = tid >> 4;
    int la_m = tid >> 1, la_k = (tid & 1) << 3;
    int lb_k = tid >> 4, lb_n = (tid & 15) << 2;

    float acc[8][4];
#pragma unroll
    for (int i=0;i<8;i++)
#pragma unroll
        for (int j=0;j<4;j++) acc[i][j]=0.f;

    int m = m0 + la_m;
    for (int k0=0;k0<512;k0+=16) {
#pragma unroll
        for (int half=0; half<2; half++) {
            int i0 = k0 + la_k + half*4;
            float4 av;
            if (i0 < 256) {
                av = *(const float4*)(g_vd + (size_t)m*256 + i0);
                av.x*=ad; av.y*=ad; av.z*=ad; av.w*=ad;
            } else {
                av = *(const float4*)(g_vn + (size_t)m*256 + i0 - 256);
                av.x*=an; av.y*=an; av.z*=an; av.w*=an;
            }
            int c = la_k + half*4;
            As[la_m][c+0]=av.x; As[la_m][c+1]=av.y; As[la_m][c+2]=av.z; As[la_m][c+3]=av.w;
        }
        float4 bv4 = *(const float4*)(Wg + (size_t)(k0+lb_k)*256 + n0 + lb_n);
        *(float4*)&Bs[lb_k][lb_n] = bv4;
        __syncthreads();
#pragma unroll
        for (int kk=0;kk<16;kk++) {
            float a[8];
#pragma unroll
            for (int i=0;i<8;i++) a[i] = As[ty*8+i][kk];
            float4 b = *(const float4*)&Bs[kk][tx*4];
#pragma unroll
            for (int i=0;i<8;i++) {
                acc[i][0]+=a[i]*b.x; acc[i][1]+=a[i]*b.y;
                acc[i][2]+=a[i]*b.z; acc[i][3]+=a[i]*b.w;
            }
        }
        __syncthreads();
    }
#pragma unroll
    for (int i=0;i<8;i++) {
        int mm = m0 + ty*8 + i;
#pragma unroll
        for (int j=0;j<4;j++) {
            int col = n0 + tx*4 + j;
            float v = acc[i][j] + bg[col];
            g_gate[(size_t)mm*256 + col] = 1.f/(1.f + __expf(-v));
        }
    }
}

// ===== SGEMM: out-proj (M=4096, N=256 x 3 chunks, K=256) + fused x_updated ====
__global__ __launch_bounds__(256) void gemm_final_kernel(
    const float* __restrict__ Wo, const float* __restrict__ bo, float* __restrict__ out)
{
    __shared__ float As[64][17];
    __shared__ float Bs[3][16][64];
    int m0 = blockIdx.x*64, n0 = blockIdx.y*64;
    int tid = threadIdx.x;
    int tx = tid & 15, ty = tid >> 4;
    int la_m = tid >> 2, la_k = (tid & 3) << 2;
    int lb_k = tid >> 4, lb_n = (tid & 15) << 2;

    float acc1[4][4], acc2[4][4], acc3[4][4];
#pragma unroll
    for (int i=0;i<4;i++)
#pragma unroll
        for (int j=0;j<4;j++) { acc1[i][j]=0.f; acc2[i][j]=0.f; acc3[i][j]=0.f; }

    for (int k0=0;k0<256;k0+=16) {
        float4 av = *(const float4*)(g_xout + (size_t)(m0+la_m)*256 + k0 + la_k);
        As[la_m][la_k+0]=av.x; As[la_m][la_k+1]=av.y; As[la_m][la_k+2]=av.z; As[la_m][la_k+3]=av.w;
#pragma unroll
        for (int ch=0; ch<3; ch++) {
            float4 bv4 = *(const float4*)(Wo + (size_t)(k0+lb_k)*768 + ch*256 + n0 + lb_n);
            *(float4*)&Bs[ch][lb_k][lb_n] = bv4;
        }
        __syncthreads();
#pragma unroll
        for (int kk=0;kk<16;kk++) {
            float a0=As[ty*4+0][kk], a1=As[ty*4+1][kk], a2=As[ty*4+2][kk], a3=As[ty*4+3][kk];
            float4 b1 = *(const float4*)&Bs[0][kk][tx*4];
            float4 b2 = *(const float4*)&Bs[1][kk][tx*4];
            float4 b3 = *(const float4*)&Bs[2][kk][tx*4];
            acc1[0][0]+=a0*b1.x; acc1[0][1]+=a0*b1.y; acc1[0][2]+=a0*b1.z; acc1[0][3]+=a0*b1.w;
            acc1[1][0]+=a1*b1.x; acc1[1][1]+=a1*b1.y; acc1[1][2]+=a1*b1.z; acc1[1][3]+=a1*b1.w;
            acc1[2][0]+=a2*b1.x; acc1[2][1]+=a2*b1.y; acc1[2][2]+=a2*b1.z; acc1[2][3]+=a2*b1.w;
            acc1[3][0]+=a3*b1.x; acc1[3][1]+=a3*b1.y; acc1[3][2]+=a3*b1.z; acc1[3][3]+=a3*b1.w;
            acc2[0][0]+=a0*b2.x; acc2[0][1]+=a0*b2.y; acc2[0][2]+=a0*b2.z; acc2[0][3]+=a0*b2.w;
            acc2[1][0]+=a1*b2.x; acc2[1][1]+=a1*b2.y; acc2[1][2]+=a1*b2.z; acc2[1][3]+=a1*b2.w;
            acc2[2][0]+=a2*b2.x; acc2[2][1]+=a2*b2.y; acc2[2][2]+=a2*b2.z; acc2[2][3]+=a2*b2.w;
            acc2[3][0]+=a3*b2.x; acc2[3][1]+=a3*b2.y; acc2[3][2]+=a3*b2.z; acc2[3][3]+=a3*b2.w;
            acc3[0][0]+=a0*b3.x; acc3[0][1]+=a0*b3.y; acc3[0][2]+=a0*b3.z; acc3[0][3]+=a0*b3.w;
            acc3[1][0]+=a1*b3.x; acc3[1][1]+=a1*b3.y; acc3[1][2]+=a1*b3.z; acc3[1][3]+=a1*b3.w;
            acc3[2][0]+=a2*b3.x; acc3[2][1]+=a2*b3.y; acc3[2][2]+=a2*b3.z; acc3[2][3]+=a2*b3.w;
            acc3[3][0]+=a3*b3.x; acc3[3][1]+=a3*b3.y; acc3[3][2]+=a3*b3.z; acc3[3][3]+=a3*b3.w;
        }
        __syncthreads();
    }
#pragma unroll
    for (int i=0;i<4;i++) {
        int m = m0 + ty*4 + i;
#pragma unroll
        for (int j=0;j<4;j++) {
            int col = n0 + tx*4 + j;
            float o1 = acc1[i][j] + bo[col];
            float o2 = acc2[i][j] + bo[256 + col];
            float o3 = acc3[i][j] + bo[512 + col];
            float vd = g_vd[(size_t)m*256 + col];
            float vn = g_vn[(size_t)m*256 + col];
            out[((size_t)m*4 + 0)*256 + col] = vd*o1 + vn*o2 + o3;  // channel 0
        }
    }
}

// ===================== vec_combined -> output channels 1..3 ===================
__global__ void combine_kernel(const float* __restrict__ x, float* __restrict__ out)
{
    int idx = blockIdx.x*blockDim.x + threadIdx.x;
    if (idx >= BN*3*256) return;
    int j  = idx & 255;
    int c  = (idx >> 8) % 3;
    int bn = idx / 768;
    float g  = g_gate[(size_t)bn*256 + j];
    float va = g_vaggr[idx];
    size_t xo = ((size_t)bn*4 + 1 + c)*256 + j;
    out[xo] = g*va + x[xo];
}

// ================================ launch ======================================
extern "C" void kernel_launch(void* const* d_in, const int* in_sizes, int n_in,
                              void* d_out, int out_size)
{
    const float* x    = (const float*)d_in[0];
    const float* Wq   = (const float*)d_in[1];
    const float* bq   = (const float*)d_in[2];
    const float* Wk   = (const float*)d_in[3];
    const float* bk   = (const float*)d_in[4];
    const float* Wv   = (const float*)d_in[5];
    const float* bv   = (const float*)d_in[6];
    const float* Wo   = (const float*)d_in[7];
    const float* bo   = (const float*)d_in[8];
    const float* Wvec = (const float*)d_in[9];
    const float* p_ad = (const float*)d_in[10];
    const float* p_an = (const float*)d_in[11];
    const float* Wg   = (const float*)d_in[12];
    const float* bg   = (const float*)d_in[13];

    float* out = (float*)d_out;
    float* attn_out = out + (size_t)BN*4*256;   // x_final first, then attn_weights

    const int attn_smem = (ROWS*KSTR*2 + ROWS*VSTR + TQ*WSTR) * 4;  // 105,216 B
    cudaFuncSetAttribute(attn_kernel, cudaFuncAttributeMaxDynamicSharedMemorySize, attn_smem);

    gemm_qkv_kernel<<<dim3(32,4,3), 256>>>(x, Wq, Wk, Wv, bq, bk, bv);
    gemm_vp_kernel<<<dim3(96,8), 256>>>(x, Wvec);
    vecdot_norm_kernel<<<BN, 256>>>(x);
    attn_kernel<<<dim3(NN/TQ,16), 256, attn_smem>>>(x, attn_out);
    gemm_gate_kernel<<<dim3(32,4), 256>>>(p_ad, p_an, Wg, bg);
    gemm_final_kernel<<<dim3(64,4), 256>>>(Wo, bo, out);
    combine_kernel<<<(BN*3*256 + 255)/256, 256>>>(x, out);
}

// round 8
// speedup vs baseline: 1.2782x; 1.2782x over previous
#include <cuda_runtime.h>
#include <cuda_bf16.h>
#include <math.h>

// Problem constants
// B=2, N=2048, H=256, heads=8, d=32, WIN=32, WIN_LEN=65
#define BB 2
#define NN 2048
#define HH 256
#define NH 8
#define HD 32
#define WIN 32
#define WLEN 65
#define BHN (BB*NH)         // 16
#define BN (BB*NN)          // 4096

// ---------------- scratch (device globals; no allocation allowed) -------------
__device__ float g_q[BHN*NN*HD];        // (bh, n, d)
__device__ float g_k[BHN*NN*HD];
__device__ float g_v[BHN*NN*HD];
__device__ float g_vp[BN*3*512];        // vec_proj (bn*3+c, 512)
__device__ float g_vd[BN*HH];           // vec_dot (bn, j)
__device__ float g_vn[BN*HH];           // vec_norm
__device__ float g_xout[BN*HH];         // x_out (bn, H)
__device__ float g_vaggr[BN*3*HH];      // (bn, c, H)
__device__ float g_gate[BN*HH];

// ======================= SGEMM: QKV (M=4096, N=256, K=256) ====================
__global__ __launch_bounds__(256) void gemm_qkv_kernel(
    const float* __restrict__ x,
    const float* __restrict__ Wq, const float* __restrict__ Wk, const float* __restrict__ Wv,
    const float* __restrict__ bq, const float* __restrict__ bk, const float* __restrict__ bv)
{
    __shared__ float As[64][17];
    __shared__ float Bs[16][64];
    int z = blockIdx.z;
    const float* W    = (z==0) ? Wq : (z==1 ? Wk : Wv);
    const float* bias = (z==0) ? bq : (z==1 ? bk : bv);
    float* dst        = (z==0) ? g_q : (z==1 ? g_k : g_v);

    int m0 = blockIdx.x*64, n0 = blockIdx.y*64;
    int tid = threadIdx.x;
    int tx = tid & 15, ty = tid >> 4;
    int la_m = tid >> 2, la_k = (tid & 3) << 2;
    int lb_k = tid >> 4, lb_n = (tid & 15) << 2;

    float acc[4][4];
#pragma unroll
    for (int i=0;i<4;i++)
#pragma unroll
        for (int j=0;j<4;j++) acc[i][j]=0.f;

    for (int k0=0;k0<256;k0+=16) {
        float4 av = *(const float4*)(x + (size_t)(m0+la_m)*1024 + k0 + la_k);
        As[la_m][la_k+0]=av.x; As[la_m][la_k+1]=av.y; As[la_m][la_k+2]=av.z; As[la_m][la_k+3]=av.w;
        float4 bv4 = *(const float4*)(W + (size_t)(k0+lb_k)*256 + n0 + lb_n);
        *(float4*)&Bs[lb_k][lb_n] = bv4;
        __syncthreads();
#pragma unroll
        for (int kk=0;kk<16;kk++) {
            float a0=As[ty*4+0][kk], a1=As[ty*4+1][kk], a2=As[ty*4+2][kk], a3=As[ty*4+3][kk];
            float4 b = *(const float4*)&Bs[kk][tx*4];
            acc[0][0]+=a0*b.x; acc[0][1]+=a0*b.y; acc[0][2]+=a0*b.z; acc[0][3]+=a0*b.w;
            acc[1][0]+=a1*b.x; acc[1][1]+=a1*b.y; acc[1][2]+=a1*b.z; acc[1][3]+=a1*b.w;
            acc[2][0]+=a2*b.x; acc[2][1]+=a2*b.y; acc[2][2]+=a2*b.z; acc[2][3]+=a2*b.w;
            acc[3][0]+=a3*b.x; acc[3][1]+=a3*b.y; acc[3][2]+=a3*b.z; acc[3][3]+=a3*b.w;
        }
        __syncthreads();
    }
#pragma unroll
    for (int i=0;i<4;i++) {
        int m = m0 + ty*4 + i;
        int b = m >> 11, n = m & 2047;
#pragma unroll
        for (int j=0;j<4;j++) {
            int col = n0 + tx*4 + j;
            int h = col >> 5, dd = col & 31;
            dst[(((size_t)(b*NH + h))*NN + n)*HD + dd] = acc[i][j] + bias[col];
        }
    }
}

// ================= SGEMM: vec_proj (M=12288, N=512, K=256) ====================
__global__ __launch_bounds__(256) void gemm_vp_kernel(
    const float* __restrict__ x, const float* __restrict__ Wvec)
{
    __shared__ float As[64][17];
    __shared__ float Bs[16][64];
    int m0 = blockIdx.x*64, n0 = blockIdx.y*64;
    int tid = threadIdx.x;
    int tx = tid & 15, ty = tid >> 4;
    int la_m = tid >> 2, la_k = (tid & 3) << 2;
    int lb_k = tid >> 4, lb_n = (tid & 15) << 2;

    float acc[4][4];
#pragma unroll
    for (int i=0;i<4;i++)
#pragma unroll
        for (int j=0;j<4;j++) acc[i][j]=0.f;

    int m = m0 + la_m;
    const float* arow = x + ((size_t)(m/3)*4 + 1 + (m%3))*256;

    for (int k0=0;k0<256;k0+=16) {
        float4 av = *(const float4*)(arow + k0 + la_k);
        As[la_m][la_k+0]=av.x; As[la_m][la_k+1]=av.y; As[la_m][la_k+2]=av.z; As[la_m][la_k+3]=av.w;
        float4 bv4 = *(const float4*)(Wvec + (size_t)(k0+lb_k)*512 + n0 + lb_n);
        *(float4*)&Bs[lb_k][lb_n] = bv4;
        __syncthreads();
#pragma unroll
        for (int kk=0;kk<16;kk++) {
            float a0=As[ty*4+0][kk], a1=As[ty*4+1][kk], a2=As[ty*4+2][kk], a3=As[ty*4+3][kk];
            float4 b = *(const float4*)&Bs[kk][tx*4];
            acc[0][0]+=a0*b.x; acc[0][1]+=a0*b.y; acc[0][2]+=a0*b.z; acc[0][3]+=a0*b.w;
            acc[1][0]+=a1*b.x; acc[1][1]+=a1*b.y; acc[1][2]+=a1*b.z; acc[1][3]+=a1*b.w;
            acc[2][0]+=a2*b.x; acc[2][1]+=a2*b.y; acc[2][2]+=a2*b.z; acc[2][3]+=a2*b.w;
            acc[3][0]+=a3*b.x; acc[3][1]+=a3*b.y; acc[3][2]+=a3*b.z; acc[3][3]+=a3*b.w;
        }
        __syncthreads();
    }
#pragma unroll
    for (int i=0;i<4;i++) {
        int mm = m0 + ty*4 + i;
#pragma unroll
        for (int j=0;j<4;j++) {
            int col = n0 + tx*4 + j;
            g_vp[(size_t)mm*512 + col] = acc[i][j];
        }
    }
}

// ============== elementwise: vec_dot and vec_norm (per bn, j) =================
__global__ void vecdot_norm_kernel(const float* __restrict__ x)
{
    int bn = blockIdx.x, j = threadIdx.x;
    float vd = 0.f, s = 0.f;
#pragma unroll
    for (int c=0;c<3;c++) {
        float a  = g_vp[((size_t)bn*3 + c)*512 + j];
        float b2 = g_vp[((size_t)bn*3 + c)*512 + 256 + j];
        vd += a*b2;
        float xv = x[((size_t)bn*4 + 1 + c)*256 + j];
        s += xv*xv;
    }
    g_vd[(size_t)bn*256 + j] = vd;
    g_vn[(size_t)bn*256 + j] = sqrtf(s);
}

// ===================== sliding-window attention (GEMM-structured) =============
// Tile: TQ=64 queries x RS=128 rows per (t, bh) block. 256 threads.
// Phase 1: scores GEMM S[64][128] = Q(64x32) . K^T(32x128), register 4x8 tiles.
// Phase 2: banded softmax on S rows (4 lanes/query, shfl reductions).
// Phase 3: aggregation GEMM O[64][128] = W(64x128, band) . VAL(128x128),
//          where VAL = [v (32) | vec c0 c1 c2 (96)]. Band-limited r loop.
#define TQ 64
#define RS 128
#define WTS_STR 132
#define KT_STR 132
#define QT_STR 68
#define VAL_STR 132
// smem (floats): wts 64*132=8448 | region: max(ksT 32*132 + qsT 32*68, val 128*132)=16896
#define SM_WTS 0
#define SM_KST 8448
#define SM_QST (8448+4224)
#define SM_VAL 8448
#define SM_TOTAL_F (8448+16896)   // 25344 floats = 101376 B

__global__ __launch_bounds__(256) void attn_kernel(
    const float* __restrict__ x, float* __restrict__ attn_out)
{
    extern __shared__ float sm[];
    float* wts = sm + SM_WTS;
    float* ksT = sm + SM_KST;
    float* qsT = sm + SM_QST;
    float* val = sm + SM_VAL;

    int t  = blockIdx.x;
    int bh = blockIdx.y;
    int b = bh >> 3, h = bh & 7;
    int n_base = t*TQ;
    int tid = threadIdx.x;

    // ---- stage K transposed: ksT[d][r] ----
    for (int idx = tid; idx < RS*32; idx += 256) {
        int r = idx >> 5, d = idx & 31;
        int ng = n_base - WIN + r;
        float kv = (ng >= 0 && ng < NN) ? g_k[((size_t)bh*NN + ng)*HD + d] : 0.f;
        ksT[d*KT_STR + r] = kv;
    }
    // ---- stage Q transposed: qsT[d][qi] ----
    for (int idx = tid; idx < TQ*32; idx += 256) {
        int qi = idx >> 5, d = idx & 31;
        qsT[d*QT_STR + qi] = g_q[((size_t)bh*NN + n_base + qi)*HD + d];
    }
    __syncthreads();

    int tx = tid & 15, ty = tid >> 4;
    int r0 = tx*8, qi0 = ty*4;

    // ---- phase 1: scores GEMM (skip fully out-of-band 4x8 blocks) ----
    {
        float acc[4][8];
#pragma unroll
        for (int i=0;i<4;i++)
#pragma unroll
            for (int j=0;j<8;j++) acc[i][j] = 0.f;

        bool active = (r0 + 7 >= qi0) && (r0 <= qi0 + 67);
        if (active) {
#pragma unroll 4
            for (int d=0; d<32; d++) {
                float4 qv = *(const float4*)&qsT[d*QT_STR + qi0];
                float4 k0 = *(const float4*)&ksT[d*KT_STR + r0];
                float4 k1 = *(const float4*)&ksT[d*KT_STR + r0 + 4];
                float qq[4] = {qv.x, qv.y, qv.z, qv.w};
                float kk[8] = {k0.x,k0.y,k0.z,k0.w,k1.x,k1.y,k1.z,k1.w};
#pragma unroll
                for (int i=0;i<4;i++)
#pragma unroll
                    for (int j=0;j<8;j++) acc[i][j] += qq[i]*kk[j];
            }
        }
        const float scale = 0.17677669529663687f;   // 1/sqrt(32)
#pragma unroll
        for (int i=0;i<4;i++) {
#pragma unroll
            for (int j=0;j<8;j+=4) {
                float4 o = make_float4(acc[i][j]*scale, acc[i][j+1]*scale,
                                       acc[i][j+2]*scale, acc[i][j+3]*scale);
                *(float4*)&wts[(qi0+i)*WTS_STR + r0 + j] = o;
            }
        }
    }
    __syncthreads();

    // ---- phase 2: banded softmax (4 lanes per query) ----
    {
        int qi = tid >> 2, p = tid & 3;
        float* row = wts + qi*WTS_STR;
        float mx = -1e30f;
        for (int w=p; w<WLEN; w+=4) mx = fmaxf(mx, row[qi + w]);
        mx = fmaxf(mx, __shfl_xor_sync(0xffffffffu, mx, 1));
        mx = fmaxf(mx, __shfl_xor_sync(0xffffffffu, mx, 2));
        float sum = 0.f;
        for (int w=p; w<WLEN; w+=4) {
            float e = __expf(row[qi + w] - mx);
            row[qi + w] = e;
            sum += e;
        }
        sum += __shfl_xor_sync(0xffffffffu, sum, 1);
        sum += __shfl_xor_sync(0xffffffffu, sum, 2);
        float inv = 1.f/sum;
        for (int w=p; w<WLEN; w+=4) row[qi + w] *= inv;
        // zero out-of-band entries (disjoint addresses from in-band writes)
        for (int r=p; r<RS; r+=4)
            if (r < qi || r > qi + WLEN - 1) row[r] = 0.f;
    }

    // ---- stage VAL[r][n]: n<32 -> v ; n>=32 -> vec channel (n-32)/32 ----
    // (overwrites ksT/qsT region; scores are done and synced)
    for (int idx = tid; idx < RS*128; idx += 256) {
        int r = idx >> 7, n = idx & 127;
        int ng = n_base - WIN + r;
        float vv = 0.f;
        if (ng >= 0 && ng < NN) {
            if (n < 32) vv = g_v[((size_t)bh*NN + ng)*HD + n];
            else {
                int c = (n-32) >> 5, dd = (n-32) & 31;
                vv = x[(((size_t)b*NN + ng)*4 + 1 + c)*256 + h*HD + dd];
            }
        }
        val[r*VAL_STR + n] = vv;
    }
    __syncthreads();

    // ---- phase 3: aggregation GEMM, band-limited r loop ----
    {
        float acc[4][8];
#pragma unroll
        for (int i=0;i<4;i++)
#pragma unroll
            for (int j=0;j<8;j++) acc[i][j] = 0.f;

        int n0 = tx*8;   // output dim block
        // band for queries qi0..qi0+3 is r in [qi0, qi0+67]
        for (int r = qi0; r <= qi0 + 67; r++) {
            float w0 = wts[(qi0+0)*WTS_STR + r];
            float w1 = wts[(qi0+1)*WTS_STR + r];
            float w2 = wts[(qi0+2)*WTS_STR + r];
            float w3 = wts[(qi0+3)*WTS_STR + r];
            float4 v0 = *(const float4*)&val[r*VAL_STR + n0];
            float4 v1 = *(const float4*)&val[r*VAL_STR + n0 + 4];
            float vv[8] = {v0.x,v0.y,v0.z,v0.w,v1.x,v1.y,v1.z,v1.w};
#pragma unroll
            for (int j=0;j<8;j++) {
                acc[0][j] += w0*vv[j];
                acc[1][j] += w1*vv[j];
                acc[2][j] += w2*vv[j];
                acc[3][j] += w3*vv[j];
            }
        }
        // write outputs: n<32 -> g_xout, else g_vaggr
#pragma unroll
        for (int i=0;i<4;i++) {
            int n = n_base + qi0 + i;
#pragma unroll
            for (int jj=0; jj<8; jj+=4) {
                int nn = n0 + jj;
                float4 o = make_float4(acc[i][jj],acc[i][jj+1],acc[i][jj+2],acc[i][jj+3]);
                if (nn < 32)
                    *(float4*)&g_xout[((size_t)b*NN + n)*HH + h*HD + nn] = o;
                else {
                    int c = (nn-32) >> 5, dd = (nn-32) & 31;
                    *(float4*)&g_vaggr[(((size_t)b*NN + n)*3 + c)*HH + h*HD + dd] = o;
                }
            }
        }
    }

    // ---- attention weights output: (bh, n, w) ----
    {
        float* ao = attn_out + ((size_t)bh*NN + n_base)*WLEN;
        for (int idx = tid; idx < TQ*WLEN; idx += 256) {
            int q2 = idx / WLEN, w = idx - q2*WLEN;
            ao[idx] = wts[q2*WTS_STR + q2 + w];
        }
    }
}

// =============== SGEMM: gate (M=4096, N=256, K=512, sigmoid) ==================
__global__ __launch_bounds__(256) void gemm_gate_kernel(
    const float* __restrict__ p_ad, const float* __restrict__ p_an,
    const float* __restrict__ Wg, const float* __restrict__ bg)
{
    __shared__ float As[64][17];
    __shared__ float Bs[16][64];
    float ad = *p_ad, an = *p_an;
    int m0 = blockIdx.x*64, n0 = blockIdx.y*64;
    int tid = threadIdx.x;
    int tx = tid & 15, ty = tid >> 4;
    int la_m = tid >> 2, la_k = (tid & 3) << 2;
    int lb_k = tid >> 4, lb_n = (tid & 15) << 2;

    float acc[4][4];
#pragma unroll
    for (int i=0;i<4;i++)
#pragma unroll
        for (int j=0;j<4;j++) acc[i][j]=0.f;

    int m = m0 + la_m;
    for (int k0=0;k0<512;k0+=16) {
        int i0 = k0 + la_k;
        float4 av;
        if (i0 < 256) {
            av = *(const float4*)(g_vd + (size_t)m*256 + i0);
            av.x*=ad; av.y*=ad; av.z*=ad; av.w*=ad;
        } else {
            av = *(const float4*)(g_vn + (size_t)m*256 + i0 - 256);
            av.x*=an; av.y*=an; av.z*=an; av.w*=an;
        }
        As[la_m][la_k+0]=av.x; As[la_m][la_k+1]=av.y; As[la_m][la_k+2]=av.z; As[la_m][la_k+3]=av.w;
        float4 bv4 = *(const float4*)(Wg + (size_t)(k0+lb_k)*256 + n0 + lb_n);
        *(float4*)&Bs[lb_k][lb_n] = bv4;
        __syncthreads();
#pragma unroll
        for (int kk=0;kk<16;kk++) {
            float a0=As[ty*4+0][kk], a1=As[ty*4+1][kk], a2=As[ty*4+2][kk], a3=As[ty*4+3][kk];
            float4 b = *(const float4*)&Bs[kk][tx*4];
            acc[0][0]+=a0*b.x; acc[0][1]+=a0*b.y; acc[0][2]+=a0*b.z; acc[0][3]+=a0*b.w;
            acc[1][0]+=a1*b.x; acc[1][1]+=a1*b.y; acc[1][2]+=a1*b.z; acc[1][3]+=a1*b.w;
            acc[2][0]+=a2*b.x; acc[2][1]+=a2*b.y; acc[2][2]+=a2*b.z; acc[2][3]+=a2*b.w;
            acc[3][0]+=a3*b.x; acc[3][1]+=a3*b.y; acc[3][2]+=a3*b.z; acc[3][3]+=a3*b.w;
        }
        __syncthreads();
    }
#pragma unroll
    for (int i=0;i<4;i++) {
        int mm = m0 + ty*4 + i;
#pragma unroll
        for (int j=0;j<4;j++) {
            int col = n0 + tx*4 + j;
            float v = acc[i][j] + bg[col];
            g_gate[(size_t)mm*256 + col] = 1.f/(1.f + __expf(-v));
        }
    }
}

// ===== SGEMM: out-proj (M=4096, N=256 x 3 chunks, K=256) + fused x_updated ====
__global__ __launch_bounds__(256) void gemm_final_kernel(
    const float* __restrict__ Wo, const float* __restrict__ bo, float* __restrict__ out)
{
    __shared__ float As[64][17];
    __shared__ float Bs[3][16][64];
    int m0 = blockIdx.x*64, n0 = blockIdx.y*64;
    int tid = threadIdx.x;
    int tx = tid & 15, ty = tid >> 4;
    int la_m = tid >> 2, la_k = (tid & 3) << 2;
    int lb_k = tid >> 4, lb_n = (tid & 15) << 2;

    float acc1[4][4], acc2[4][4], acc3[4][4];
#pragma unroll
    for (int i=0;i<4;i++)
#pragma unroll
        for (int j=0;j<4;j++) { acc1[i][j]=0.f; acc2[i][j]=0.f; acc3[i][j]=0.f; }

    for (int k0=0;k0<256;k0+=16) {
        float4 av = *(const float4*)(g_xout + (size_t)(m0+la_m)*256 + k0 + la_k);
        As[la_m][la_k+0]=av.x; As[la_m][la_k+1]=av.y; As[la_m][la_k+2]=av.z; As[la_m][la_k+3]=av.w;
#pragma unroll
        for (int ch=0; ch<3; ch++) {
            float4 bv4 = *(const float4*)(Wo + (size_t)(k0+lb_k)*768 + ch*256 + n0 + lb_n);
            *(float4*)&Bs[ch][lb_k][lb_n] = bv4;
        }
        __syncthreads();
#pragma unroll
        for (int kk=0;kk<16;kk++) {
            float a0=As[ty*4+0][kk], a1=As[ty*4+1][kk], a2=As[ty*4+2][kk], a3=As[ty*4+3][kk];
            float4 b1 = *(const float4*)&Bs[0][kk][tx*4];
            float4 b2 = *(const float4*)&Bs[1][kk][tx*4];
            float4 b3 = *(const float4*)&Bs[2][kk][tx*4];
            acc1[0][0]+=a0*b1.x; acc1[0][1]+=a0*b1.y; acc1[0][2]+=a0*b1.z; acc1[0][3]+=a0*b1.w;
            acc1[1][0]+=a1*b1.x; acc1[1][1]+=a1*b1.y; acc1[1][2]+=a1*b1.z; acc1[1][3]+=a1*b1.w;
            acc1[2][0]+=a2*b1.x; acc1[2][1]+=a2*b1.y; acc1[2][2]+=a2*b1.z; acc1[2][3]+=a2*b1.w;
            acc1[3][0]+=a3*b1.x; acc1[3][1]+=a3*b1.y; acc1[3][2]+=a3*b1.z; acc1[3][3]+=a3*b1.w;
            acc2[0][0]+=a0*b2.x; acc2[0][1]+=a0*b2.y; acc2[0][2]+=a0*b2.z; acc2[0][3]+=a0*b2.w;
            acc2[1][0]+=a1*b2.x; acc2[1][1]+=a1*b2.y; acc2[1][2]+=a1*b2.z; acc2[1][3]+=a1*b2.w;
            acc2[2][0]+=a2*b2.x; acc2[2][1]+=a2*b2.y; acc2[2][2]+=a2*b2.z; acc2[2][3]+=a2*b2.w;
            acc2[3][0]+=a3*b2.x; acc2[3][1]+=a3*b2.y; acc2[3][2]+=a3*b2.z; acc2[3][3]+=a3*b2.w;
            acc3[0][0]+=a0*b3.x; acc3[0][1]+=a0*b3.y; acc3[0][2]+=a0*b3.z; acc3[0][3]+=a0*b3.w;
            acc3[1][0]+=a1*b3.x; acc3[1][1]+=a1*b3.y; acc3[1][2]+=a1*b3.z; acc3[1][3]+=a1*b3.w;
            acc3[2][0]+=a2*b3.x; acc3[2][1]+=a2*b3.y; acc3[2][2]+=a2*b3.z; acc3[2][3]+=a2*b3.w;
            acc3[3][0]+=a3*b3.x; acc3[3][1]+=a3*b3.y; acc3[3][2]+=a3*b3.z; acc3[3][3]+=a3*b3.w;
        }
        __syncthreads();
    }
#pragma unroll
    for (int i=0;i<4;i++) {
        int m = m0 + ty*4 + i;
#pragma unroll
        for (int j=0;j<4;j++) {
            int col = n0 + tx*4 + j;
            float o1 = acc1[i][j] + bo[col];
            float o2 = acc2[i][j] + bo[256 + col];
            float o3 = acc3[i][j] + bo[512 + col];
            float vd = g_vd[(size_t)m*256 + col];
            float vn = g_vn[(size_t)m*256 + col];
            out[((size_t)m*4 + 0)*256 + col] = vd*o1 + vn*o2 + o3;  // channel 0
        }
    }
}

// ===================== vec_combined -> output channels 1..3 ===================
__global__ void combine_kernel(const float* __restrict__ x, float* __restrict__ out)
{
    int idx = blockIdx.x*blockDim.x + threadIdx.x;
    if (idx >= BN*3*256) return;
    int j  = idx & 255;
    int c  = (idx >> 8) % 3;
    int bn = idx / 768;
    float g  = g_gate[(size_t)bn*256 + j];
    float va = g_vaggr[idx];
    size_t xo = ((size_t)bn*4 + 1 + c)*256 + j;
    out[xo] = g*va + x[xo];
}

// ================================ launch ======================================
extern "C" void kernel_launch(void* const* d_in, const int* in_sizes, int n_in,
                              void* d_out, int out_size)
{
    const float* x    = (const float*)d_in[0];
    const float* Wq   = (const float*)d_in[1];
    const float* bq   = (const float*)d_in[2];
    const float* Wk   = (const float*)d_in[3];
    const float* bk   = (const float*)d_in[4];
    const float* Wv   = (const float*)d_in[5];
    const float* bv   = (const float*)d_in[6];
    const float* Wo   = (const float*)d_in[7];
    const float* bo   = (const float*)d_in[8];
    const float* Wvec = (const float*)d_in[9];
    const float* p_ad = (const float*)d_in[10];
    const float* p_an = (const float*)d_in[11];
    const float* Wg   = (const float*)d_in[12];
    const float* bg   = (const float*)d_in[13];

    float* out = (float*)d_out;
    float* attn_out = out + (size_t)BN*4*256;   // x_final first, then attn_weights

    const int attn_smem = SM_TOTAL_F * 4;       // 101,376 B
    cudaFuncSetAttribute(attn_kernel, cudaFuncAttributeMaxDynamicSharedMemorySize, attn_smem);

    gemm_qkv_kernel<<<dim3(64,4,3), 256>>>(x, Wq, Wk, Wv, bq, bk, bv);
    gemm_vp_kernel<<<dim3(192,8), 256>>>(x, Wvec);
    vecdot_norm_kernel<<<BN, 256>>>(x);
    attn_kernel<<<dim3(NN/TQ,16), 256, attn_smem>>>(x, attn_out);
    gemm_gate_kernel<<<dim3(64,4), 256>>>(p_ad, p_an, Wg, bg);
    gemm_final_kernel<<<dim3(64,4), 256>>>(Wo, bo, out);
    combine_kernel<<<(BN*3*256 + 255)/256, 256>>>(x, out);
}

// round 12
// speedup vs baseline: 1.9016x; 1.4878x over previous
#include <cuda_runtime.h>
#include <cuda_bf16.h>
#include <math.h>
#include <stdint.h>

// Problem constants
// B=2, N=2048, H=256, heads=8, d=32, WIN=32, WIN_LEN=65
#define BB 2
#define NN 2048
#define HH 256
#define NH 8
#define HD 32
#define WIN 32
#define WLEN 65
#define BHN (BB*NH)         // 16
#define BN (BB*NN)          // 4096

// ---------------- scratch (device globals; no allocation allowed) -------------
__device__ float g_q[BHN*NN*HD];        // (bh, n, d)
__device__ float g_k[BHN*NN*HD];
__device__ float g_v[BHN*NN*HD];
__device__ float g_vp[BN*3*512];        // vec_proj (bn*3+c, 512)
__device__ float g_vd[BN*HH];           // vec_dot (bn, j)
__device__ float g_vn[BN*HH];           // vec_norm
__device__ float g_xout[BN*HH];         // x_out (bn, H)
__device__ float g_vaggr[BN*3*HH];      // (bn, c, H)
__device__ float g_gate[BN*HH];
__device__ float g_o[BN*768];           // out-proj scratch (m, 768)

// ========================= tf32 mma helpers ==================================
__device__ __forceinline__ uint32_t f2tf32(float f) {
    uint32_t r;
    asm("cvt.rna.tf32.f32 %0, %1;" : "=r"(r) : "f"(f));
    return r;
}

__device__ __forceinline__ void mma_tf32(float* c, const uint32_t* a, const uint32_t* b) {
    asm volatile(
        "mma.sync.aligned.m16n8k8.row.col.f32.tf32.tf32.f32 "
        "{%0,%1,%2,%3}, {%4,%5,%6,%7}, {%8,%9}, {%0,%1,%2,%3};\n"
        : "+f"(c[0]), "+f"(c[1]), "+f"(c[2]), "+f"(c[3])
        : "r"(a[0]), "r"(a[1]), "r"(a[2]), "r"(a[3]), "r"(b[0]), "r"(b[1]));
}

// Smem strides (uint32 words). AST=20, BST=72: both map the 32-lane fragment
// load patterns onto all 32 banks exactly once (conflict-free).
#define AST 20
#define BST 72

// Core 64x64x16 tf32 tile loop. 256 threads, 8 warps (2m x 4n), each warp
// computes 32x16 via 2x2 m16n8k8 fragments. A row-major [64x16], B row-major
// [16x64] staged per k-step. Caller supplies lambdas-by-macro for A/B loads.
// acc layout: acc[mi][ni][4].

// ======================= tf32 GEMM: QKV (M=4096,N=256,K=256) ==================
__global__ __launch_bounds__(256) void gemm_qkv_kernel(
    const float* __restrict__ x,
    const float* __restrict__ Wq, const float* __restrict__ Wk, const float* __restrict__ Wv,
    const float* __restrict__ bq, const float* __restrict__ bk, const float* __restrict__ bv)
{
    __shared__ uint32_t As[64*AST];
    __shared__ uint32_t Bs[16*BST];
    int z = blockIdx.z;
    const float* W    = (z==0) ? Wq : (z==1 ? Wk : Wv);
    const float* bias = (z==0) ? bq : (z==1 ? bk : bv);
    float* dst        = (z==0) ? g_q : (z==1 ? g_k : g_v);

    int m0 = blockIdx.x*64, n0 = blockIdx.y*64;
    int tid = threadIdx.x;
    int lane = tid & 31, w = tid >> 5;
    int wm = w >> 2, wn = w & 3;
    int rq = lane >> 2, rr = lane & 3;
    int la_m = tid >> 2, la_k = (tid & 3) << 2;
    int lb_k = tid >> 4, lb_n = (tid & 15) << 2;

    float acc[2][2][4];
#pragma unroll
    for (int i=0;i<2;i++)
#pragma unroll
        for (int j=0;j<2;j++)
#pragma unroll
            for (int c=0;c<4;c++) acc[i][j][c]=0.f;

    const float* arow = x + (size_t)(m0+la_m)*1024;

    for (int k0=0;k0<256;k0+=16) {
        float4 av = *(const float4*)(arow + k0 + la_k);
        As[la_m*AST + la_k+0]=f2tf32(av.x); As[la_m*AST + la_k+1]=f2tf32(av.y);
        As[la_m*AST + la_k+2]=f2tf32(av.z); As[la_m*AST + la_k+3]=f2tf32(av.w);
        float4 bv4 = *(const float4*)(W + (size_t)(k0+lb_k)*256 + n0 + lb_n);
        Bs[lb_k*BST + lb_n+0]=f2tf32(bv4.x); Bs[lb_k*BST + lb_n+1]=f2tf32(bv4.y);
        Bs[lb_k*BST + lb_n+2]=f2tf32(bv4.z); Bs[lb_k*BST + lb_n+3]=f2tf32(bv4.w);
        __syncthreads();
#pragma unroll
        for (int ks=0;ks<16;ks+=8) {
            uint32_t a[2][4], b[2][2];
#pragma unroll
            for (int mi=0;mi<2;mi++) {
                int rb = wm*32 + mi*16 + rq;
                a[mi][0] = As[(rb  )*AST + ks + rr];
                a[mi][1] = As[(rb+8)*AST + ks + rr];
                a[mi][2] = As[(rb  )*AST + ks + 4 + rr];
                a[mi][3] = As[(rb+8)*AST + ks + 4 + rr];
            }
#pragma unroll
            for (int ni=0;ni<2;ni++) {
                int cb = wn*16 + ni*8 + rq;
                b[ni][0] = Bs[(ks   + rr)*BST + cb];
                b[ni][1] = Bs[(ks+4 + rr)*BST + cb];
            }
#pragma unroll
            for (int mi=0;mi<2;mi++)
#pragma unroll
                for (int ni=0;ni<2;ni++) mma_tf32(acc[mi][ni], a[mi], b[ni]);
        }
        __syncthreads();
    }
    // epilogue: scatter (b,h,n,d) + bias
#pragma unroll
    for (int mi=0;mi<2;mi++) {
#pragma unroll
        for (int ni=0;ni<2;ni++) {
            int col = n0 + wn*16 + ni*8 + 2*rr;
            int h = col >> 5, dd = col & 31;
            float b0 = bias[col], b1 = bias[col+1];
#pragma unroll
            for (int half=0; half<2; half++) {
                int m = m0 + wm*32 + mi*16 + rq + half*8;
                int bb = m >> 11, n = m & 2047;
                float2 o = make_float2(acc[mi][ni][half*2+0] + b0,
                                       acc[mi][ni][half*2+1] + b1);
                *(float2*)&dst[(((size_t)(bb*NH + h))*NN + n)*HD + dd] = o;
            }
        }
    }
}

// =================== tf32 GEMM: vec_proj (M=12288,N=512,K=256) ================
__global__ __launch_bounds__(256) void gemm_vp_kernel(
    const float* __restrict__ x, const float* __restrict__ Wvec)
{
    __shared__ uint32_t As[64*AST];
    __shared__ uint32_t Bs[16*BST];
    int m0 = blockIdx.x*64, n0 = blockIdx.y*64;
    int tid = threadIdx.x;
    int lane = tid & 31, w = tid >> 5;
    int wm = w >> 2, wn = w & 3;
    int rq = lane >> 2, rr = lane & 3;
    int la_m = tid >> 2, la_k = (tid & 3) << 2;
    int lb_k = tid >> 4, lb_n = (tid & 15) << 2;

    float acc[2][2][4];
#pragma unroll
    for (int i=0;i<2;i++)
#pragma unroll
        for (int j=0;j<2;j++)
#pragma unroll
            for (int c=0;c<4;c++) acc[i][j][c]=0.f;

    int m = m0 + la_m;
    const float* arow = x + ((size_t)(m/3)*4 + 1 + (m%3))*256;

    for (int k0=0;k0<256;k0+=16) {
        float4 av = *(const float4*)(arow + k0 + la_k);
        As[la_m*AST + la_k+0]=f2tf32(av.x); As[la_m*AST + la_k+1]=f2tf32(av.y);
        As[la_m*AST + la_k+2]=f2tf32(av.z); As[la_m*AST + la_k+3]=f2tf32(av.w);
        float4 bv4 = *(const float4*)(Wvec + (size_t)(k0+lb_k)*512 + n0 + lb_n);
        Bs[lb_k*BST + lb_n+0]=f2tf32(bv4.x); Bs[lb_k*BST + lb_n+1]=f2tf32(bv4.y);
        Bs[lb_k*BST + lb_n+2]=f2tf32(bv4.z); Bs[lb_k*BST + lb_n+3]=f2tf32(bv4.w);
        __syncthreads();
#pragma unroll
        for (int ks=0;ks<16;ks+=8) {
            uint32_t a[2][4], b[2][2];
#pragma unroll
            for (int mi=0;mi<2;mi++) {
                int rb = wm*32 + mi*16 + rq;
                a[mi][0] = As[(rb  )*AST + ks + rr];
                a[mi][1] = As[(rb+8)*AST + ks + rr];
                a[mi][2] = As[(rb  )*AST + ks + 4 + rr];
                a[mi][3] = As[(rb+8)*AST + ks + 4 + rr];
            }
#pragma unroll
            for (int ni=0;ni<2;ni++) {
                int cb = wn*16 + ni*8 + rq;
                b[ni][0] = Bs[(ks   + rr)*BST + cb];
                b[ni][1] = Bs[(ks+4 + rr)*BST + cb];
            }
#pragma unroll
            for (int mi=0;mi<2;mi++)
#pragma unroll
                for (int ni=0;ni<2;ni++) mma_tf32(acc[mi][ni], a[mi], b[ni]);
        }
        __syncthreads();
    }
#pragma unroll
    for (int mi=0;mi<2;mi++) {
#pragma unroll
        for (int ni=0;ni<2;ni++) {
            int col = n0 + wn*16 + ni*8 + 2*rr;
#pragma unroll
            for (int half=0; half<2; half++) {
                int mm = m0 + wm*32 + mi*16 + rq + half*8;
                float2 o = make_float2(acc[mi][ni][half*2+0], acc[mi][ni][half*2+1]);
                *(float2*)&g_vp[(size_t)mm*512 + col] = o;
            }
        }
    }
}

// ============== elementwise: vec_dot and vec_norm (per bn, j) =================
__global__ void vecdot_norm_kernel(const float* __restrict__ x)
{
    int bn = blockIdx.x, j = threadIdx.x;
    float vd = 0.f, s = 0.f;
#pragma unroll
    for (int c=0;c<3;c++) {
        float a  = g_vp[((size_t)bn*3 + c)*512 + j];
        float b2 = g_vp[((size_t)bn*3 + c)*512 + 256 + j];
        vd += a*b2;
        float xv = x[((size_t)bn*4 + 1 + c)*256 + j];
        s += xv*xv;
    }
    g_vd[(size_t)bn*256 + j] = vd;
    g_vn[(size_t)bn*256 + j] = sqrtf(s);
}

// ===================== sliding-window attention (GEMM-structured) =============
#define TQ 64
#define RS 128
#define WTS_STR 132
#define KT_STR 132
#define QT_STR 68
#define VAL_STR 132
#define SM_WTS 0
#define SM_KST 8448
#define SM_QST (8448+4224)
#define SM_VAL 8448
#define SM_TOTAL_F (8448+16896)   // 25344 floats = 101376 B

__global__ __launch_bounds__(256) void attn_kernel(
    const float* __restrict__ x, float* __restrict__ attn_out)
{
    extern __shared__ float sm[];
    float* wts = sm + SM_WTS;
    float* ksT = sm + SM_KST;
    float* qsT = sm + SM_QST;
    float* val = sm + SM_VAL;

    int t  = blockIdx.x;
    int bh = blockIdx.y;
    int b = bh >> 3, h = bh & 7;
    int n_base = t*TQ;
    int tid = threadIdx.x;

    for (int idx = tid; idx < RS*32; idx += 256) {
        int r = idx >> 5, d = idx & 31;
        int ng = n_base - WIN + r;
        float kv = (ng >= 0 && ng < NN) ? g_k[((size_t)bh*NN + ng)*HD + d] : 0.f;
        ksT[d*KT_STR + r] = kv;
    }
    for (int idx = tid; idx < TQ*32; idx += 256) {
        int qi = idx >> 5, d = idx & 31;
        qsT[d*QT_STR + qi] = g_q[((size_t)bh*NN + n_base + qi)*HD + d];
    }
    __syncthreads();

    int tx = tid & 15, ty = tid >> 4;
    int r0 = tx*8, qi0 = ty*4;

    {
        float acc[4][8];
#pragma unroll
        for (int i=0;i<4;i++)
#pragma unroll
            for (int j=0;j<8;j++) acc[i][j] = 0.f;

        bool active = (r0 + 7 >= qi0) && (r0 <= qi0 + 67);
        if (active) {
#pragma unroll 4
            for (int d=0; d<32; d++) {
                float4 qv = *(const float4*)&qsT[d*QT_STR + qi0];
                float4 k0 = *(const float4*)&ksT[d*KT_STR + r0];
                float4 k1 = *(const float4*)&ksT[d*KT_STR + r0 + 4];
                float qq[4] = {qv.x, qv.y, qv.z, qv.w};
                float kk[8] = {k0.x,k0.y,k0.z,k0.w,k1.x,k1.y,k1.z,k1.w};
#pragma unroll
                for (int i=0;i<4;i++)
#pragma unroll
                    for (int j=0;j<8;j++) acc[i][j] += qq[i]*kk[j];
            }
        }
        const float scale = 0.17677669529663687f;   // 1/sqrt(32)
#pragma unroll
        for (int i=0;i<4;i++) {
#pragma unroll
            for (int j=0;j<8;j+=4) {
                float4 o = make_float4(acc[i][j]*scale, acc[i][j+1]*scale,
                                       acc[i][j+2]*scale, acc[i][j+3]*scale);
                *(float4*)&wts[(qi0+i)*WTS_STR + r0 + j] = o;
            }
        }
    }
    __syncthreads();

    {
        int qi = tid >> 2, p = tid & 3;
        float* row = wts + qi*WTS_STR;
        float mx = -1e30f;
        for (int w=p; w<WLEN; w+=4) mx = fmaxf(mx, row[qi + w]);
        mx = fmaxf(mx, __shfl_xor_sync(0xffffffffu, mx, 1));
        mx = fmaxf(mx, __shfl_xor_sync(0xffffffffu, mx, 2));
        float sum = 0.f;
        for (int w=p; w<WLEN; w+=4) {
            float e = __expf(row[qi + w] - mx);
            row[qi + w] = e;
            sum += e;
        }
        sum += __shfl_xor_sync(0xffffffffu, sum, 1);
        sum += __shfl_xor_sync(0xffffffffu, sum, 2);
        float inv = 1.f/sum;
        for (int w=p; w<WLEN; w+=4) row[qi + w] *= inv;
        for (int r=p; r<RS; r+=4)
            if (r < qi || r > qi + WLEN - 1) row[r] = 0.f;
    }

    for (int idx = tid; idx < RS*128; idx += 256) {
        int r = idx >> 7, n = idx & 127;
        int ng = n_base - WIN + r;
        float vv = 0.f;
        if (ng >= 0 && ng < NN) {
            if (n < 32) vv = g_v[((size_t)bh*NN + ng)*HD + n];
            else {
                int c = (n-32) >> 5, dd = (n-32) & 31;
                vv = x[(((size_t)b*NN + ng)*4 + 1 + c)*256 + h*HD + dd];
            }
        }
        val[r*VAL_STR + n] = vv;
    }
    __syncthreads();

    {
        float acc[4][8];
#pragma unroll
        for (int i=0;i<4;i++)
#pragma unroll
            for (int j=0;j<8;j++) acc[i][j] = 0.f;

        int n0 = tx*8;
        for (int r = qi0; r <= qi0 + 67; r++) {
            float w0 = wts[(qi0+0)*WTS_STR + r];
            float w1 = wts[(qi0+1)*WTS_STR + r];
            float w2 = wts[(qi0+2)*WTS_STR + r];
            float w3 = wts[(qi0+3)*WTS_STR + r];
            float4 v0 = *(const float4*)&val[r*VAL_STR + n0];
            float4 v1 = *(const float4*)&val[r*VAL_STR + n0 + 4];
            float vv[8] = {v0.x,v0.y,v0.z,v0.w,v1.x,v1.y,v1.z,v1.w};
#pragma unroll
            for (int j=0;j<8;j++) {
                acc[0][j] += w0*vv[j];
                acc[1][j] += w1*vv[j];
                acc[2][j] += w2*vv[j];
                acc[3][j] += w3*vv[j];
            }
        }
#pragma unroll
        for (int i=0;i<4;i++) {
            int n = n_base + qi0 + i;
#pragma unroll
            for (int jj=0; jj<8; jj+=4) {
                int nn = n0 + jj;
                float4 o = make_float4(acc[i][jj],acc[i][jj+1],acc[i][jj+2],acc[i][jj+3]);
                if (nn < 32)
                    *(float4*)&g_xout[((size_t)b*NN + n)*HH + h*HD + nn] = o;
                else {
                    int c = (nn-32) >> 5, dd = (nn-32) & 31;
                    *(float4*)&g_vaggr[(((size_t)b*NN + n)*3 + c)*HH + h*HD + dd] = o;
                }
            }
        }
    }

    {
        float* ao = attn_out + ((size_t)bh*NN + n_base)*WLEN;
        for (int idx = tid; idx < TQ*WLEN; idx += 256) {
            int q2 = idx / WLEN, w = idx - q2*WLEN;
            ao[idx] = wts[q2*WTS_STR + q2 + w];
        }
    }
}

// ============ tf32 GEMM: gate (M=4096,N=256,K=512) + sigmoid ==================
__global__ __launch_bounds__(256) void gemm_gate_kernel(
    const float* __restrict__ p_ad, const float* __restrict__ p_an,
    const float* __restrict__ Wg, const float* __restrict__ bg)
{
    __shared__ uint32_t As[64*AST];
    __shared__ uint32_t Bs[16*BST];
    float ad = *p_ad, an = *p_an;
    int m0 = blockIdx.x*64, n0 = blockIdx.y*64;
    int tid = threadIdx.x;
    int lane = tid & 31, w = tid >> 5;
    int wm = w >> 2, wn = w & 3;
    int rq = lane >> 2, rr = lane & 3;
    int la_m = tid >> 2, la_k = (tid & 3) << 2;
    int lb_k = tid >> 4, lb_n = (tid & 15) << 2;

    float acc[2][2][4];
#pragma unroll
    for (int i=0;i<2;i++)
#pragma unroll
        for (int j=0;j<2;j++)
#pragma unroll
            for (int c=0;c<4;c++) acc[i][j][c]=0.f;

    int m = m0 + la_m;
    for (int k0=0;k0<512;k0+=16) {
        int i0 = k0 + la_k;
        float4 av;
        if (i0 < 256) {
            av = *(const float4*)(g_vd + (size_t)m*256 + i0);
            av.x*=ad; av.y*=ad; av.z*=ad; av.w*=ad;
        } else {
            av = *(const float4*)(g_vn + (size_t)m*256 + i0 - 256);
            av.x*=an; av.y*=an; av.z*=an; av.w*=an;
        }
        As[la_m*AST + la_k+0]=f2tf32(av.x); As[la_m*AST + la_k+1]=f2tf32(av.y);
        As[la_m*AST + la_k+2]=f2tf32(av.z); As[la_m*AST + la_k+3]=f2tf32(av.w);
        float4 bv4 = *(const float4*)(Wg + (size_t)(k0+lb_k)*256 + n0 + lb_n);
        Bs[lb_k*BST + lb_n+0]=f2tf32(bv4.x); Bs[lb_k*BST + lb_n+1]=f2tf32(bv4.y);
        Bs[lb_k*BST + lb_n+2]=f2tf32(bv4.z); Bs[lb_k*BST + lb_n+3]=f2tf32(bv4.w);
        __syncthreads();
#pragma unroll
        for (int ks=0;ks<16;ks+=8) {
            uint32_t a[2][4], b[2][2];
#pragma unroll
            for (int mi=0;mi<2;mi++) {
                int rb = wm*32 + mi*16 + rq;
                a[mi][0] = As[(rb  )*AST + ks + rr];
                a[mi][1] = As[(rb+8)*AST + ks + rr];
                a[mi][2] = As[(rb  )*AST + ks + 4 + rr];
                a[mi][3] = As[(rb+8)*AST + ks + 4 + rr];
            }
#pragma unroll
            for (int ni=0;ni<2;ni++) {
                int cb = wn*16 + ni*8 + rq;
                b[ni][0] = Bs[(ks   + rr)*BST + cb];
                b[ni][1] = Bs[(ks+4 + rr)*BST + cb];
            }
#pragma unroll
            for (int mi=0;mi<2;mi++)
#pragma unroll
                for (int ni=0;ni<2;ni++) mma_tf32(acc[mi][ni], a[mi], b[ni]);
        }
        __syncthreads();
    }
#pragma unroll
    for (int mi=0;mi<2;mi++) {
#pragma unroll
        for (int ni=0;ni<2;ni++) {
            int col = n0 + wn*16 + ni*8 + 2*rr;
            float b0 = bg[col], b1 = bg[col+1];
#pragma unroll
            for (int half=0; half<2; half++) {
                int mm = m0 + wm*32 + mi*16 + rq + half*8;
                float v0 = acc[mi][ni][half*2+0] + b0;
                float v1 = acc[mi][ni][half*2+1] + b1;
                float2 o = make_float2(1.f/(1.f + __expf(-v0)), 1.f/(1.f + __expf(-v1)));
                *(float2*)&g_gate[(size_t)mm*256 + col] = o;
            }
        }
    }
}

// ============ tf32 GEMM: out-proj (M=4096,N=768,K=256) -> g_o =================
__global__ __launch_bounds__(256) void gemm_final_kernel(const float* __restrict__ Wo)
{
    __shared__ uint32_t As[64*AST];
    __shared__ uint32_t Bs[16*BST];
    int m0 = blockIdx.x*64, n0 = blockIdx.y*64;
    int tid = threadIdx.x;
    int lane = tid & 31, w = tid >> 5;
    int wm = w >> 2, wn = w & 3;
    int rq = lane >> 2, rr = lane & 3;
    int la_m = tid >> 2, la_k = (tid & 3) << 2;
    int lb_k = tid >> 4, lb_n = (tid & 15) << 2;

    float acc[2][2][4];
#pragma unroll
    for (int i=0;i<2;i++)
#pragma unroll
        for (int j=0;j<2;j++)
#pragma unroll
            for (int c=0;c<4;c++) acc[i][j][c]=0.f;

    for (int k0=0;k0<256;k0+=16) {
        float4 av = *(const float4*)(g_xout + (size_t)(m0+la_m)*256 + k0 + la_k);
        As[la_m*AST + la_k+0]=f2tf32(av.x); As[la_m*AST + la_k+1]=f2tf32(av.y);
        As[la_m*AST + la_k+2]=f2tf32(av.z); As[la_m*AST + la_k+3]=f2tf32(av.w);
        float4 bv4 = *(const float4*)(Wo + (size_t)(k0+lb_k)*768 + n0 + lb_n);
        Bs[lb_k*BST + lb_n+0]=f2tf32(bv4.x); Bs[lb_k*BST + lb_n+1]=f2tf32(bv4.y);
        Bs[lb_k*BST + lb_n+2]=f2tf32(bv4.z); Bs[lb_k*BST + lb_n+3]=f2tf32(bv4.w);
        __syncthreads();
#pragma unroll
        for (int ks=0;ks<16;ks+=8) {
            uint32_t a[2][4], b[2][2];
#pragma unroll
            for (int mi=0;mi<2;mi++) {
                int rb = wm*32 + mi*16 + rq;
                a[mi][0] = As[(rb  )*AST + ks + rr];
                a[mi][1] = As[(rb+8)*AST + ks + rr];
                a[mi][2] = As[(rb  )*AST + ks + 4 + rr];
                a[mi][3] = As[(rb+8)*AST + ks + 4 + rr];
            }
#pragma unroll
            for (int ni=0;ni<2;ni++) {
                int cb = wn*16 + ni*8 + rq;
                b[ni][0] = Bs[(ks   + rr)*BST + cb];
                b[ni][1] = Bs[(ks+4 + rr)*BST + cb];
            }
#pragma unroll
            for (int mi=0;mi<2;mi++)
#pragma unroll
                for (int ni=0;ni<2;ni++) mma_tf32(acc[mi][ni], a[mi], b[ni]);
        }
        __syncthreads();
    }
#pragma unroll
    for (int mi=0;mi<2;mi++) {
#pragma unroll
        for (int ni=0;ni<2;ni++) {
            int col = n0 + wn*16 + ni*8 + 2*rr;
#pragma unroll
            for (int half=0; half<2; half++) {
                int mm = m0 + wm*32 + mi*16 + rq + half*8;
                float2 o = make_float2(acc[mi][ni][half*2+0], acc[mi][ni][half*2+1]);
                *(float2*)&g_o[(size_t)mm*768 + col] = o;
            }
        }
    }
}

// ======= finalize channel 0: x_updated = vd*o1 + vn*o2 + o3 (+ biases) ========
__global__ void finalize_kernel(const float* __restrict__ bo, float* __restrict__ out)
{
    int idx = blockIdx.x*blockDim.x + threadIdx.x;
    if (idx >= BN*256) return;
    int m = idx >> 8, j = idx & 255;
    float o1 = g_o[(size_t)m*768 + j]       + bo[j];
    float o2 = g_o[(size_t)m*768 + 256 + j] + bo[256 + j];
    float o3 = g_o[(size_t)m*768 + 512 + j] + bo[512 + j];
    float vd = g_vd[(size_t)m*256 + j];
    float vn = g_vn[(size_t)m*256 + j];
    out[((size_t)m*4 + 0)*256 + j] = vd*o1 + vn*o2 + o3;
}

// ===================== vec_combined -> output channels 1..3 ===================
__global__ void combine_kernel(const float* __restrict__ x, float* __restrict__ out)
{
    int idx = blockIdx.x*blockDim.x + threadIdx.x;
    if (idx >= BN*3*256) return;
    int j  = idx & 255;
    int c  = (idx >> 8) % 3;
    int bn = idx / 768;
    float g  = g_gate[(size_t)bn*256 + j];
    float va = g_vaggr[idx];
    size_t xo = ((size_t)bn*4 + 1 + c)*256 + j;
    out[xo] = g*va + x[xo];
}

// ================================ launch ======================================
extern "C" void kernel_launch(void* const* d_in, const int* in_sizes, int n_in,
                              void* d_out, int out_size)
{
    const float* x    = (const float*)d_in[0];
    const float* Wq   = (const float*)d_in[1];
    const float* bq   = (const float*)d_in[2];
    const float* Wk   = (const float*)d_in[3];
    const float* bk   = (const float*)d_in[4];
    const float* Wv   = (const float*)d_in[5];
    const float* bv   = (const float*)d_in[6];
    const float* Wo   = (const float*)d_in[7];
    const float* bo   = (const float*)d_in[8];
    const float* Wvec = (const float*)d_in[9];
    const float* p_ad = (const float*)d_in[10];
    const float* p_an = (const float*)d_in[11];
    const float* Wg   = (const float*)d_in[12];
    const float* bg   = (const float*)d_in[13];

    float* out = (float*)d_out;
    float* attn_out = out + (size_t)BN*4*256;   // x_final first, then attn_weights

    const int attn_smem = SM_TOTAL_F * 4;       // 101,376 B
    cudaFuncSetAttribute(attn_kernel, cudaFuncAttributeMaxDynamicSharedMemorySize, attn_smem);

    gemm_qkv_kernel<<<dim3(64,4,3), 256>>>(x, Wq, Wk, Wv, bq, bk, bv);
    gemm_vp_kernel<<<dim3(192,8), 256>>>(x, Wvec);
    vecdot_norm_kernel<<<BN, 256>>>(x);
    attn_kernel<<<dim3(NN/TQ,16), 256, attn_smem>>>(x, attn_out);
    gemm_gate_kernel<<<dim3(64,4), 256>>>(p_ad, p_an, Wg, bg);
    gemm_final_kernel<<<dim3(64,12), 256>>>(Wo);
    finalize_kernel<<<(BN*256 + 255)/256, 256>>>(bo, out);
    combine_kernel<<<(BN*3*256 + 255)/256, 256>>>(x, out);
}

// round 15
// speedup vs baseline: 2.1072x; 1.1081x over previous
#include <cuda_runtime.h>
#include <cuda_bf16.h>
#include <math.h>
#include <stdint.h>

// Problem constants
// B=2, N=2048, H=256, heads=8, d=32, WIN=32, WIN_LEN=65
#define BB 2
#define NN 2048
#define HH 256
#define NH 8
#define HD 32
#define WIN 32
#define WLEN 65
#define BHN (BB*NH)         // 16
#define BN (BB*NN)          // 4096

// ---------------- scratch (device globals; no allocation allowed) -------------
__device__ float g_q[BHN*NN*HD];        // (bh, n, d)
__device__ float g_k[BHN*NN*HD];
__device__ float g_v[BHN*NN*HD];
__device__ float g_vp[BN*3*512];        // vec_proj (bn*3+c, 512)
__device__ float g_vd[BN*HH];           // vec_dot (bn, j)
__device__ float g_vn[BN*HH];           // vec_norm
__device__ float g_xout[BN*HH];         // x_out (bn, H)
__device__ float g_vaggr[BN*3*HH];      // (bn, c, H)
__device__ float g_gate[BN*HH];
__device__ float g_o[BN*768];           // out-proj scratch (m, 768)

// ========================= tf32 mma helpers ==================================
__device__ __forceinline__ uint32_t f2tf32(float f) {
    uint32_t r;
    asm("cvt.rna.tf32.f32 %0, %1;" : "=r"(r) : "f"(f));
    return r;
}
__device__ __forceinline__ float f2tf32f(float f) {
    return __uint_as_float(f2tf32(f));
}

__device__ __forceinline__ void mma_tf32(float* c, const uint32_t* a, const uint32_t* b) {
    asm volatile(
        "mma.sync.aligned.m16n8k8.row.col.f32.tf32.tf32.f32 "
        "{%0,%1,%2,%3}, {%4,%5,%6,%7}, {%8,%9}, {%0,%1,%2,%3};\n"
        : "+f"(c[0]), "+f"(c[1]), "+f"(c[2]), "+f"(c[3])
        : "r"(a[0]), "r"(a[1]), "r"(a[2]), "r"(a[3]), "r"(b[0]), "r"(b[1]));
}

// Smem strides (uint32 words). AST=20, BST=72: conflict-free fragment loads.
#define AST 20
#define BST 72

// ======================= tf32 GEMM: QKV (M=4096,N=256,K=256) ==================
__global__ __launch_bounds__(256) void gemm_qkv_kernel(
    const float* __restrict__ x,
    const float* __restrict__ Wq, const float* __restrict__ Wk, const float* __restrict__ Wv,
    const float* __restrict__ bq, const float* __restrict__ bk, const float* __restrict__ bv)
{
    __shared__ uint32_t As[64*AST];
    __shared__ uint32_t Bs[16*BST];
    int z = blockIdx.z;
    const float* W    = (z==0) ? Wq : (z==1 ? Wk : Wv);
    const float* bias = (z==0) ? bq : (z==1 ? bk : bv);
    float* dst        = (z==0) ? g_q : (z==1 ? g_k : g_v);

    int m0 = blockIdx.x*64, n0 = blockIdx.y*64;
    int tid = threadIdx.x;
    int lane = tid & 31, w = tid >> 5;
    int wm = w >> 2, wn = w & 3;
    int rq = lane >> 2, rr = lane & 3;
    int la_m = tid >> 2, la_k = (tid & 3) << 2;
    int lb_k = tid >> 4, lb_n = (tid & 15) << 2;

    float acc[2][2][4];
#pragma unroll
    for (int i=0;i<2;i++)
#pragma unroll
        for (int j=0;j<2;j++)
#pragma unroll
            for (int c=0;c<4;c++) acc[i][j][c]=0.f;

    const float* arow = x + (size_t)(m0+la_m)*1024;

    for (int k0=0;k0<256;k0+=16) {
        float4 av = *(const float4*)(arow + k0 + la_k);
        As[la_m*AST + la_k+0]=f2tf32(av.x); As[la_m*AST + la_k+1]=f2tf32(av.y);
        As[la_m*AST + la_k+2]=f2tf32(av.z); As[la_m*AST + la_k+3]=f2tf32(av.w);
        float4 bv4 = *(const float4*)(W + (size_t)(k0+lb_k)*256 + n0 + lb_n);
        Bs[lb_k*BST + lb_n+0]=f2tf32(bv4.x); Bs[lb_k*BST + lb_n+1]=f2tf32(bv4.y);
        Bs[lb_k*BST + lb_n+2]=f2tf32(bv4.z); Bs[lb_k*BST + lb_n+3]=f2tf32(bv4.w);
        __syncthreads();
#pragma unroll
        for (int ks=0;ks<16;ks+=8) {
            uint32_t a[2][4], b[2][2];
#pragma unroll
            for (int mi=0;mi<2;mi++) {
                int rb = wm*32 + mi*16 + rq;
                a[mi][0] = As[(rb  )*AST + ks + rr];
                a[mi][1] = As[(rb+8)*AST + ks + rr];
                a[mi][2] = As[(rb  )*AST + ks + 4 + rr];
                a[mi][3] = As[(rb+8)*AST + ks + 4 + rr];
            }
#pragma unroll
            for (int ni=0;ni<2;ni++) {
                int cb = wn*16 + ni*8 + rq;
                b[ni][0] = Bs[(ks   + rr)*BST + cb];
                b[ni][1] = Bs[(ks+4 + rr)*BST + cb];
            }
#pragma unroll
            for (int mi=0;mi<2;mi++)
#pragma unroll
                for (int ni=0;ni<2;ni++) mma_tf32(acc[mi][ni], a[mi], b[ni]);
        }
        __syncthreads();
    }
#pragma unroll
    for (int mi=0;mi<2;mi++) {
#pragma unroll
        for (int ni=0;ni<2;ni++) {
            int col = n0 + wn*16 + ni*8 + 2*rr;
            int h = col >> 5, dd = col & 31;
            float b0 = bias[col], b1 = bias[col+1];
#pragma unroll
            for (int half=0; half<2; half++) {
                int m = m0 + wm*32 + mi*16 + rq + half*8;
                int bb = m >> 11, n = m & 2047;
                float2 o = make_float2(acc[mi][ni][half*2+0] + b0,
                                       acc[mi][ni][half*2+1] + b1);
                *(float2*)&dst[(((size_t)(bb*NH + h))*NN + n)*HD + dd] = o;
            }
        }
    }
}

// =================== tf32 GEMM: vec_proj (M=12288,N=512,K=256) ================
__global__ __launch_bounds__(256) void gemm_vp_kernel(
    const float* __restrict__ x, const float* __restrict__ Wvec)
{
    __shared__ uint32_t As[64*AST];
    __shared__ uint32_t Bs[16*BST];
    int m0 = blockIdx.x*64, n0 = blockIdx.y*64;
    int tid = threadIdx.x;
    int lane = tid & 31, w = tid >> 5;
    int wm = w >> 2, wn = w & 3;
    int rq = lane >> 2, rr = lane & 3;
    int la_m = tid >> 2, la_k = (tid & 3) << 2;
    int lb_k = tid >> 4, lb_n = (tid & 15) << 2;

    float acc[2][2][4];
#pragma unroll
    for (int i=0;i<2;i++)
#pragma unroll
        for (int j=0;j<2;j++)
#pragma unroll
            for (int c=0;c<4;c++) acc[i][j][c]=0.f;

    int m = m0 + la_m;
    const float* arow = x + ((size_t)(m/3)*4 + 1 + (m%3))*256;

    for (int k0=0;k0<256;k0+=16) {
        float4 av = *(const float4*)(arow + k0 + la_k);
        As[la_m*AST + la_k+0]=f2tf32(av.x); As[la_m*AST + la_k+1]=f2tf32(av.y);
        As[la_m*AST + la_k+2]=f2tf32(av.z); As[la_m*AST + la_k+3]=f2tf32(av.w);
        float4 bv4 = *(const float4*)(Wvec + (size_t)(k0+lb_k)*512 + n0 + lb_n);
        Bs[lb_k*BST + lb_n+0]=f2tf32(bv4.x); Bs[lb_k*BST + lb_n+1]=f2tf32(bv4.y);
        Bs[lb_k*BST + lb_n+2]=f2tf32(bv4.z); Bs[lb_k*BST + lb_n+3]=f2tf32(bv4.w);
        __syncthreads();
#pragma unroll
        for (int ks=0;ks<16;ks+=8) {
            uint32_t a[2][4], b[2][2];
#pragma unroll
            for (int mi=0;mi<2;mi++) {
                int rb = wm*32 + mi*16 + rq;
                a[mi][0] = As[(rb  )*AST + ks + rr];
                a[mi][1] = As[(rb+8)*AST + ks + rr];
                a[mi][2] = As[(rb  )*AST + ks + 4 + rr];
                a[mi][3] = As[(rb+8)*AST + ks + 4 + rr];
            }
#pragma unroll
            for (int ni=0;ni<2;ni++) {
                int cb = wn*16 + ni*8 + rq;
                b[ni][0] = Bs[(ks   + rr)*BST + cb];
                b[ni][1] = Bs[(ks+4 + rr)*BST + cb];
            }
#pragma unroll
            for (int mi=0;mi<2;mi++)
#pragma unroll
                for (int ni=0;ni<2;ni++) mma_tf32(acc[mi][ni], a[mi], b[ni]);
        }
        __syncthreads();
    }
#pragma unroll
    for (int mi=0;mi<2;mi++) {
#pragma unroll
        for (int ni=0;ni<2;ni++) {
            int col = n0 + wn*16 + ni*8 + 2*rr;
#pragma unroll
            for (int half=0; half<2; half++) {
                int mm = m0 + wm*32 + mi*16 + rq + half*8;
                float2 o = make_float2(acc[mi][ni][half*2+0], acc[mi][ni][half*2+1]);
                *(float2*)&g_vp[(size_t)mm*512 + col] = o;
            }
        }
    }
}

// ============== elementwise: vec_dot and vec_norm (per bn, j) =================
__global__ void vecdot_norm_kernel(const float* __restrict__ x)
{
    int bn = blockIdx.x, j = threadIdx.x;
    float vd = 0.f, s = 0.f;
#pragma unroll
    for (int c=0;c<3;c++) {
        float a  = g_vp[((size_t)bn*3 + c)*512 + j];
        float b2 = g_vp[((size_t)bn*3 + c)*512 + 256 + j];
        vd += a*b2;
        float xv = x[((size_t)bn*4 + 1 + c)*256 + j];
        s += xv*xv;
    }
    g_vd[(size_t)bn*256 + j] = vd;
    g_vn[(size_t)bn*256 + j] = sqrtf(s);
}

// ============== sliding-window attention (tensor-core tf32) ===================
// Block: (t, bh), 256 threads, 8 warps (wm 2 x wn 4).
// Phase 1: S[64][128] = Q(64x32) . K^T(32x128)   via m16n8k8.tf32
// Phase 2: banded softmax (fp32, exact); attn_out written pre-rounding;
//          weights tf32-rounded in place for phase 3.
// Phase 3: O[64][128] = W(64x128) . VAL(128x128) via m16n8k8.tf32
//          VAL = [v (32) | vec c0 c1 c2 (96)], out-of-band W entries = 0.
#define TQ 64
#define RS 128
#define WSTR 132      // wts stride (stride%32==4 -> conflict-free A pattern)
#define QST  36       // qs stride  (%32==4)
#define KTS  136      // ksT stride (%32==8 -> conflict-free B pattern)
#define VST  136      // val stride (%32==8)
#define SM_WTS 0                  // 64*132  = 8448
#define SM_QS  8448               // 64*36   = 2304
#define SM_KST (8448+2304)        // 32*136  = 4352  (end 15104)
#define SM_VAL 8448               // 128*136 = 17408 (overlaps qs+ksT after P1)
#define SM_TOTAL_F (8448+17408)   // 25856 floats = 103424 B

__global__ __launch_bounds__(256) void attn_kernel(
    const float* __restrict__ x, float* __restrict__ attn_out)
{
    extern __shared__ float sm[];
    float* wts = sm + SM_WTS;
    float* qs  = sm + SM_QS;
    float* ksT = sm + SM_KST;
    float* val = sm + SM_VAL;

    int t  = blockIdx.x;
    int bh = blockIdx.y;
    int b = bh >> 3, h = bh & 7;
    int n_base = t*TQ;
    int tid = threadIdx.x;
    int lane = tid & 31, w = tid >> 5;
    int wm = w >> 2, wn = w & 3;
    int rq = lane >> 2, rr = lane & 3;

    // ---- stage K^T (tf32) and Q (tf32) ----
    for (int idx = tid; idx < RS*32; idx += 256) {
        int r = idx >> 5, d = idx & 31;
        int ng = n_base - WIN + r;
        float kv = (ng >= 0 && ng < NN) ? g_k[((size_t)bh*NN + ng)*HD + d] : 0.f;
        ksT[d*KTS + r] = f2tf32f(kv);
    }
    for (int idx = tid; idx < TQ*32; idx += 256) {
        int qi = idx >> 5, d = idx & 31;
        qs[qi*QST + d] = f2tf32f(g_q[((size_t)bh*NN + n_base + qi)*HD + d]);
    }
    __syncthreads();

    // ---- phase 1: scores via mma (M=64, N=128, K=32) ----
    {
        float acc[2][4][4];
#pragma unroll
        for (int i=0;i<2;i++)
#pragma unroll
            for (int j=0;j<4;j++)
#pragma unroll
                for (int c=0;c<4;c++) acc[i][j][c]=0.f;

#pragma unroll
        for (int ks=0;ks<32;ks+=8) {
            uint32_t a[2][4], bfr[4][2];
#pragma unroll
            for (int mi=0;mi<2;mi++) {
                int rb = wm*32 + mi*16 + rq;
                a[mi][0] = ((const uint32_t*)qs)[(rb  )*QST + ks + rr];
                a[mi][1] = ((const uint32_t*)qs)[(rb+8)*QST + ks + rr];
                a[mi][2] = ((const uint32_t*)qs)[(rb  )*QST + ks + 4 + rr];
                a[mi][3] = ((const uint32_t*)qs)[(rb+8)*QST + ks + 4 + rr];
            }
#pragma unroll
            for (int ni=0;ni<4;ni++) {
                int cb = wn*32 + ni*8 + rq;
                bfr[ni][0] = ((const uint32_t*)ksT)[(ks   + rr)*KTS + cb];
                bfr[ni][1] = ((const uint32_t*)ksT)[(ks+4 + rr)*KTS + cb];
            }
#pragma unroll
            for (int mi=0;mi<2;mi++)
#pragma unroll
                for (int ni=0;ni<4;ni++) mma_tf32(acc[mi][ni], a[mi], bfr[ni]);
        }
        const float scale = 0.17677669529663687f;   // 1/sqrt(32)
#pragma unroll
        for (int mi=0;mi<2;mi++) {
#pragma unroll
            for (int ni=0;ni<4;ni++) {
                int col = wn*32 + ni*8 + 2*rr;
#pragma unroll
                for (int half=0; half<2; half++) {
                    int row = wm*32 + mi*16 + rq + half*8;
                    float2 o = make_float2(acc[mi][ni][half*2+0]*scale,
                                           acc[mi][ni][half*2+1]*scale);
                    *(float2*)&wts[row*WSTR + col] = o;
                }
            }
        }
    }
    __syncthreads();

    // ---- stage VAL (tf32) — overwrites qs/ksT; scores already in wts ----
    for (int idx = tid; idx < RS*128; idx += 256) {
        int r = idx >> 7, n = idx & 127;
        int ng = n_base - WIN + r;
        float vv = 0.f;
        if (ng >= 0 && ng < NN) {
            if (n < 32) vv = g_v[((size_t)bh*NN + ng)*HD + n];
            else {
                int c = (n-32) >> 5, dd = (n-32) & 31;
                vv = x[(((size_t)b*NN + ng)*4 + 1 + c)*256 + h*HD + dd];
            }
        }
        val[r*VST + n] = f2tf32f(vv);
    }

    // ---- phase 2: banded softmax (exact fp32; rows owned by 4-lane groups) ----
    {
        int qi = tid >> 2, p = tid & 3;
        float* row = wts + qi*WSTR;
        float mx = -1e30f;
        for (int w2=p; w2<WLEN; w2+=4) mx = fmaxf(mx, row[qi + w2]);
        mx = fmaxf(mx, __shfl_xor_sync(0xffffffffu, mx, 1));
        mx = fmaxf(mx, __shfl_xor_sync(0xffffffffu, mx, 2));
        float sum = 0.f;
        for (int w2=p; w2<WLEN; w2+=4) {
            float e = __expf(row[qi + w2] - mx);
            row[qi + w2] = e;
            sum += e;
        }
        sum += __shfl_xor_sync(0xffffffffu, sum, 1);
        sum += __shfl_xor_sync(0xffffffffu, sum, 2);
        float inv = 1.f/sum;
        float* ao = attn_out + ((size_t)bh*NN + n_base + qi)*WLEN;
        for (int w2=p; w2<WLEN; w2+=4) {
            float v = row[qi + w2]*inv;
            ao[w2] = v;                           // exact fp32 out
            row[qi + w2] = f2tf32f(v);            // rounded for mma
        }
        for (int r=p; r<RS; r+=4)
            if (r < qi || r > qi + WLEN - 1) row[r] = 0.f;
    }
    __syncthreads();

    // ---- phase 3: aggregation via mma (M=64, N=128, K=128) ----
    {
        float acc[2][4][4];
#pragma unroll
        for (int i=0;i<2;i++)
#pragma unroll
            for (int j=0;j<4;j++)
#pragma unroll
                for (int c=0;c<4;c++) acc[i][j][c]=0.f;

        for (int ks=0;ks<128;ks+=8) {
            uint32_t a[2][4], bfr[4][2];
#pragma unroll
            for (int mi=0;mi<2;mi++) {
                int rb = wm*32 + mi*16 + rq;
                a[mi][0] = ((const uint32_t*)wts)[(rb  )*WSTR + ks + rr];
                a[mi][1] = ((const uint32_t*)wts)[(rb+8)*WSTR + ks + rr];
                a[mi][2] = ((const uint32_t*)wts)[(rb  )*WSTR + ks + 4 + rr];
                a[mi][3] = ((const uint32_t*)wts)[(rb+8)*WSTR + ks + 4 + rr];
            }
#pragma unroll
            for (int ni=0;ni<4;ni++) {
                int cb = wn*32 + ni*8 + rq;
                bfr[ni][0] = ((const uint32_t*)val)[(ks   + rr)*VST + cb];
                bfr[ni][1] = ((const uint32_t*)val)[(ks+4 + rr)*VST + cb];
            }
#pragma unroll
            for (int mi=0;mi<2;mi++)
#pragma unroll
                for (int ni=0;ni<4;ni++) mma_tf32(acc[mi][ni], a[mi], bfr[ni]);
        }

        // epilogue: wn==0 -> g_xout (dims 0..31); wn>=1 -> g_vaggr channel wn-1
#pragma unroll
        for (int mi=0;mi<2;mi++) {
#pragma unroll
            for (int ni=0;ni<4;ni++) {
                int dd = ni*8 + 2*rr;
#pragma unroll
                for (int half=0; half<2; half++) {
                    int qrow = wm*32 + mi*16 + rq + half*8;
                    int n = n_base + qrow;
                    float2 o = make_float2(acc[mi][ni][half*2+0], acc[mi][ni][half*2+1]);
                    if (wn == 0)
                        *(float2*)&g_xout[((size_t)b*NN + n)*HH + h*HD + dd] = o;
                    else
                        *(float2*)&g_vaggr[(((size_t)b*NN + n)*3 + (wn-1))*HH + h*HD + dd] = o;
                }
            }
        }
    }
}

// ============ tf32 GEMM: gate (M=4096,N=256,K=512) + sigmoid ==================
__global__ __launch_bounds__(256) void gemm_gate_kernel(
    const float* __restrict__ p_ad, const float* __restrict__ p_an,
    const float* __restrict__ Wg, const float* __restrict__ bg)
{
    __shared__ uint32_t As[64*AST];
    __shared__ uint32_t Bs[16*BST];
    float ad = *p_ad, an = *p_an;
    int m0 = blockIdx.x*64, n0 = blockIdx.y*64;
    int tid = threadIdx.x;
    int lane = tid & 31, w = tid >> 5;
    int wm = w >> 2, wn = w & 3;
    int rq = lane >> 2, rr = lane & 3;
    int la_m = tid >> 2, la_k = (tid & 3) << 2;
    int lb_k = tid >> 4, lb_n = (tid & 15) << 2;

    float acc[2][2][4];
#pragma unroll
    for (int i=0;i<2;i++)
#pragma unroll
        for (int j=0;j<2;j++)
#pragma unroll
            for (int c=0;c<4;c++) acc[i][j][c]=0.f;

    int m = m0 + la_m;
    for (int k0=0;k0<512;k0+=16) {
        int i0 = k0 + la_k;
        float4 av;
        if (i0 < 256) {
            av = *(const float4*)(g_vd + (size_t)m*256 + i0);
            av.x*=ad; av.y*=ad; av.z*=ad; av.w*=ad;
        } else {
            av = *(const float4*)(g_vn + (size_t)m*256 + i0 - 256);
            av.x*=an; av.y*=an; av.z*=an; av.w*=an;
        }
        As[la_m*AST + la_k+0]=f2tf32(av.x); As[la_m*AST + la_k+1]=f2tf32(av.y);
        As[la_m*AST + la_k+2]=f2tf32(av.z); As[la_m*AST + la_k+3]=f2tf32(av.w);
        float4 bv4 = *(const float4*)(Wg + (size_t)(k0+lb_k)*256 + n0 + lb_n);
        Bs[lb_k*BST + lb_n+0]=f2tf32(bv4.x); Bs[lb_k*BST + lb_n+1]=f2tf32(bv4.y);
        Bs[lb_k*BST + lb_n+2]=f2tf32(bv4.z); Bs[lb_k*BST + lb_n+3]=f2tf32(bv4.w);
        __syncthreads();
#pragma unroll
        for (int ks=0;ks<16;ks+=8) {
            uint32_t a[2][4], b[2][2];
#pragma unroll
            for (int mi=0;mi<2;mi++) {
                int rb = wm*32 + mi*16 + rq;
                a[mi][0] = As[(rb  )*AST + ks + rr];
                a[mi][1] = As[(rb+8)*AST + ks + rr];
                a[mi][2] = As[(rb  )*AST + ks + 4 + rr];
                a[mi][3] = As[(rb+8)*AST + ks + 4 + rr];
            }
#pragma unroll
            for (int ni=0;ni<2;ni++) {
                int cb = wn*16 + ni*8 + rq;
                b[ni][0] = Bs[(ks   + rr)*BST + cb];
                b[ni][1] = Bs[(ks+4 + rr)*BST + cb];
            }
#pragma unroll
            for (int mi=0;mi<2;mi++)
#pragma unroll
                for (int ni=0;ni<2;ni++) mma_tf32(acc[mi][ni], a[mi], b[ni]);
        }
        __syncthreads();
    }
#pragma unroll
    for (int mi=0;mi<2;mi++) {
#pragma unroll
        for (int ni=0;ni<2;ni++) {
            int col = n0 + wn*16 + ni*8 + 2*rr;
            float b0 = bg[col], b1 = bg[col+1];
#pragma unroll
            for (int half=0; half<2; half++) {
                int mm = m0 + wm*32 + mi*16 + rq + half*8;
                float v0 = acc[mi][ni][half*2+0] + b0;
                float v1 = acc[mi][ni][half*2+1] + b1;
                float2 o = make_float2(1.f/(1.f + __expf(-v0)), 1.f/(1.f + __expf(-v1)));
                *(float2*)&g_gate[(size_t)mm*256 + col] = o;
            }
        }
    }
}

// ============ tf32 GEMM: out-proj (M=4096,N=768,K=256) -> g_o =================
__global__ __launch_bounds__(256) void gemm_final_kernel(const float* __restrict__ Wo)
{
    __shared__ uint32_t As[64*AST];
    __shared__ uint32_t Bs[16*BST];
    int m0 = blockIdx.x*64, n0 = blockIdx.y*64;
    int tid = threadIdx.x;
    int lane = tid & 31, w = tid >> 5;
    int wm = w >> 2, wn = w & 3;
    int rq = lane >> 2, rr = lane & 3;
    int la_m = tid >> 2, la_k = (tid & 3) << 2;
    int lb_k = tid >> 4, lb_n = (tid & 15) << 2;

    float acc[2][2][4];
#pragma unroll
    for (int i=0;i<2;i++)
#pragma unroll
        for (int j=0;j<2;j++)
#pragma unroll
            for (int c=0;c<4;c++) acc[i][j][c]=0.f;

    for (int k0=0;k0<256;k0+=16) {
        float4 av = *(const float4*)(g_xout + (size_t)(m0+la_m)*256 + k0 + la_k);
        As[la_m*AST + la_k+0]=f2tf32(av.x); As[la_m*AST + la_k+1]=f2tf32(av.y);
        As[la_m*AST + la_k+2]=f2tf32(av.z); As[la_m*AST + la_k+3]=f2tf32(av.w);
        float4 bv4 = *(const float4*)(Wo + (size_t)(k0+lb_k)*768 + n0 + lb_n);
        Bs[lb_k*BST + lb_n+0]=f2tf32(bv4.x); Bs[lb_k*BST + lb_n+1]=f2tf32(bv4.y);
        Bs[lb_k*BST + lb_n+2]=f2tf32(bv4.z); Bs[lb_k*BST + lb_n+3]=f2tf32(bv4.w);
        __syncthreads();
#pragma unroll
        for (int ks=0;ks<16;ks+=8) {
            uint32_t a[2][4], b[2][2];
#pragma unroll
            for (int mi=0;mi<2;mi++) {
                int rb = wm*32 + mi*16 + rq;
                a[mi][0] = As[(rb  )*AST + ks + rr];
                a[mi][1] = As[(rb+8)*AST + ks + rr];
                a[mi][2] = As[(rb  )*AST + ks + 4 + rr];
                a[mi][3] = As[(rb+8)*AST + ks + 4 + rr];
            }
#pragma unroll
            for (int ni=0;ni<2;ni++) {
                int cb = wn*16 + ni*8 + rq;
                b[ni][0] = Bs[(ks   + rr)*BST + cb];
                b[ni][1] = Bs[(ks+4 + rr)*BST + cb];
            }
#pragma unroll
            for (int mi=0;mi<2;mi++)
#pragma unroll
                for (int ni=0;ni<2;ni++) mma_tf32(acc[mi][ni], a[mi], b[ni]);
        }
        __syncthreads();
    }
#pragma unroll
    for (int mi=0;mi<2;mi++) {
#pragma unroll
        for (int ni=0;ni<2;ni++) {
            int col = n0 + wn*16 + ni*8 + 2*rr;
#pragma unroll
            for (int half=0; half<2; half++) {
                int mm = m0 + wm*32 + mi*16 + rq + half*8;
                float2 o = make_float2(acc[mi][ni][half*2+0], acc[mi][ni][half*2+1]);
                *(float2*)&g_o[(size_t)mm*768 + col] = o;
            }
        }
    }
}

// ======= finalize channel 0: x_updated = vd*o1 + vn*o2 + o3 (+ biases) ========
__global__ void finalize_kernel(const float* __restrict__ bo, float* __restrict__ out)
{
    int idx = blockIdx.x*blockDim.x + threadIdx.x;
    if (idx >= BN*256) return;
    int m = idx >> 8, j = idx & 255;
    float o1 = g_o[(size_t)m*768 + j]       + bo[j];
    float o2 = g_o[(size_t)m*768 + 256 + j] + bo[256 + j];
    float o3 = g_o[(size_t)m*768 + 512 + j] + bo[512 + j];
    float vd = g_vd[(size_t)m*256 + j];
    float vn = g_vn[(size_t)m*256 + j];
    out[((size_t)m*4 + 0)*256 + j] = vd*o1 + vn*o2 + o3;
}

// ===================== vec_combined -> output channels 1..3 ===================
__global__ void combine_kernel(const float* __restrict__ x, float* __restrict__ out)
{
    int idx = blockIdx.x*blockDim.x + threadIdx.x;
    if (idx >= BN*3*256) return;
    int j  = idx & 255;
    int c  = (idx >> 8) % 3;
    int bn = idx / 768;
    float g  = g_gate[(size_t)bn*256 + j];
    float va = g_vaggr[idx];
    size_t xo = ((size_t)bn*4 + 1 + c)*256 + j;
    out[xo] = g*va + x[xo];
}

// ================================ launch ======================================
extern "C" void kernel_launch(void* const* d_in, const int* in_sizes, int n_in,
                              void* d_out, int out_size)
{
    const float* x    = (const float*)d_in[0];
    const float* Wq   = (const float*)d_in[1];
    const float* bq   = (const float*)d_in[2];
    const float* Wk   = (const float*)d_in[3];
    const float* bk   = (const float*)d_in[4];
    const float* Wv   = (const float*)d_in[5];
    const float* bv   = (const float*)d_in[6];
    const float* Wo   = (const float*)d_in[7];
    const float* bo   = (const float*)d_in[8];
    const float* Wvec = (const float*)d_in[9];
    const float* p_ad = (const float*)d_in[10];
    const float* p_an = (const float*)d_in[11];
    const float* Wg   = (const float*)d_in[12];
    const float* bg   = (const float*)d_in[13];

    float* out = (float*)d_out;
    float* attn_out = out + (size_t)BN*4*256;   // x_final first, then attn_weights

    const int attn_smem = SM_TOTAL_F * 4;       // 103,424 B
    cudaFuncSetAttribute(attn_kernel, cudaFuncAttributeMaxDynamicSharedMemorySize, attn_smem);

    gemm_qkv_kernel<<<dim3(64,4,3), 256>>>(x, Wq, Wk, Wv, bq, bk, bv);
    gemm_vp_kernel<<<dim3(192,8), 256>>>(x, Wvec);
    vecdot_norm_kernel<<<BN, 256>>>(x);
    attn_kernel<<<dim3(NN/TQ,16), 256, attn_smem>>>(x, attn_out);
    gemm_gate_kernel<<<dim3(64,4), 256>>>(p_ad, p_an, Wg, bg);
    gemm_final_kernel<<<dim3(64,12), 256>>>(Wo);
    finalize_kernel<<<(BN*256 + 255)/256, 256>>>(bo, out);
    combine_kernel<<<(BN*3*256 + 255)/256, 256>>>(x, out);
}

// round 16
// speedup vs baseline: 2.5196x; 1.1957x over previous
#include <cuda_runtime.h>
#include <cuda_bf16.h>
#include <math.h>
#include <stdint.h>

// Problem constants
// B=2, N=2048, H=256, heads=8, d=32, WIN=32, WIN_LEN=65
#define BB 2
#define NN 2048
#define HH 256
#define NH 8
#define HD 32
#define WIN 32
#define WLEN 65
#define BHN (BB*NH)         // 16
#define BN (BB*NN)          // 4096

// ---------------- scratch (device globals; no allocation allowed) -------------
__device__ float g_q[BHN*NN*HD];        // (bh, n, d)
__device__ float g_k[BHN*NN*HD];
__device__ float g_v[BHN*NN*HD];
__device__ float g_vp[BN*3*512];        // vec_proj (bn*3+c, 512)
__device__ float g_vd[BN*HH];           // vec_dot (bn, j)
__device__ float g_vn[BN*HH];           // vec_norm
__device__ float g_xout[BN*HH];         // x_out (bn, H)
__device__ float g_vaggr[BN*3*HH];      // (bn, c, H)
__device__ float g_gate[BN*HH];
__device__ float g_o[BN*768];           // out-proj scratch (m, 768)

// ========================= tf32 mma helpers ==================================
__device__ __forceinline__ uint32_t f2tf32(float f) {
    uint32_t r;
    asm("cvt.rna.tf32.f32 %0, %1;" : "=r"(r) : "f"(f));
    return r;
}
__device__ __forceinline__ float f2tf32f(float f) {
    return __uint_as_float(f2tf32(f));
}

__device__ __forceinline__ void mma_tf32(float* c, const uint32_t* a, const uint32_t* b) {
    asm volatile(
        "mma.sync.aligned.m16n8k8.row.col.f32.tf32.tf32.f32 "
        "{%0,%1,%2,%3}, {%4,%5,%6,%7}, {%8,%9}, {%0,%1,%2,%3};\n"
        : "+f"(c[0]), "+f"(c[1]), "+f"(c[2]), "+f"(c[3])
        : "r"(a[0]), "r"(a[1]), "r"(a[2]), "r"(a[3]), "r"(b[0]), "r"(b[1]));
}

// Smem strides (uint32 words). AST=20, BST=72: conflict-free fragment loads.
#define AST 20
#define BST 72

// ======================= tf32 GEMM: QKV (M=4096,N=256,K=256) ==================
__global__ __launch_bounds__(256) void gemm_qkv_kernel(
    const float* __restrict__ x,
    const float* __restrict__ Wq, const float* __restrict__ Wk, const float* __restrict__ Wv,
    const float* __restrict__ bq, const float* __restrict__ bk, const float* __restrict__ bv)
{
    __shared__ uint32_t As[64*AST];
    __shared__ uint32_t Bs[16*BST];
    int z = blockIdx.z;
    const float* W    = (z==0) ? Wq : (z==1 ? Wk : Wv);
    const float* bias = (z==0) ? bq : (z==1 ? bk : bv);
    float* dst        = (z==0) ? g_q : (z==1 ? g_k : g_v);

    int m0 = blockIdx.x*64, n0 = blockIdx.y*64;
    int tid = threadIdx.x;
    int lane = tid & 31, w = tid >> 5;
    int wm = w >> 2, wn = w & 3;
    int rq = lane >> 2, rr = lane & 3;
    int la_m = tid >> 2, la_k = (tid & 3) << 2;
    int lb_k = tid >> 4, lb_n = (tid & 15) << 2;

    float acc[2][2][4];
#pragma unroll
    for (int i=0;i<2;i++)
#pragma unroll
        for (int j=0;j<2;j++)
#pragma unroll
            for (int c=0;c<4;c++) acc[i][j][c]=0.f;

    const float* arow = x + (size_t)(m0+la_m)*1024;

    for (int k0=0;k0<256;k0+=16) {
        float4 av = *(const float4*)(arow + k0 + la_k);
        As[la_m*AST + la_k+0]=f2tf32(av.x); As[la_m*AST + la_k+1]=f2tf32(av.y);
        As[la_m*AST + la_k+2]=f2tf32(av.z); As[la_m*AST + la_k+3]=f2tf32(av.w);
        float4 bv4 = *(const float4*)(W + (size_t)(k0+lb_k)*256 + n0 + lb_n);
        Bs[lb_k*BST + lb_n+0]=f2tf32(bv4.x); Bs[lb_k*BST + lb_n+1]=f2tf32(bv4.y);
        Bs[lb_k*BST + lb_n+2]=f2tf32(bv4.z); Bs[lb_k*BST + lb_n+3]=f2tf32(bv4.w);
        __syncthreads();
#pragma unroll
        for (int ks=0;ks<16;ks+=8) {
            uint32_t a[2][4], b[2][2];
#pragma unroll
            for (int mi=0;mi<2;mi++) {
                int rb = wm*32 + mi*16 + rq;
                a[mi][0] = As[(rb  )*AST + ks + rr];
                a[mi][1] = As[(rb+8)*AST + ks + rr];
                a[mi][2] = As[(rb  )*AST + ks + 4 + rr];
                a[mi][3] = As[(rb+8)*AST + ks + 4 + rr];
            }
#pragma unroll
            for (int ni=0;ni<2;ni++) {
                int cb = wn*16 + ni*8 + rq;
                b[ni][0] = Bs[(ks   + rr)*BST + cb];
                b[ni][1] = Bs[(ks+4 + rr)*BST + cb];
            }
#pragma unroll
            for (int mi=0;mi<2;mi++)
#pragma unroll
                for (int ni=0;ni<2;ni++) mma_tf32(acc[mi][ni], a[mi], b[ni]);
        }
        __syncthreads();
    }
#pragma unroll
    for (int mi=0;mi<2;mi++) {
#pragma unroll
        for (int ni=0;ni<2;ni++) {
            int col = n0 + wn*16 + ni*8 + 2*rr;
            int h = col >> 5, dd = col & 31;
            float b0 = bias[col], b1 = bias[col+1];
#pragma unroll
            for (int half=0; half<2; half++) {
                int m = m0 + wm*32 + mi*16 + rq + half*8;
                int bb = m >> 11, n = m & 2047;
                float2 o = make_float2(acc[mi][ni][half*2+0] + b0,
                                       acc[mi][ni][half*2+1] + b1);
                *(float2*)&dst[(((size_t)(bb*NH + h))*NN + n)*HD + dd] = o;
            }
        }
    }
}

// =================== tf32 GEMM: vec_proj (M=12288,N=512,K=256) ================
__global__ __launch_bounds__(256) void gemm_vp_kernel(
    const float* __restrict__ x, const float* __restrict__ Wvec)
{
    __shared__ uint32_t As[64*AST];
    __shared__ uint32_t Bs[16*BST];
    int m0 = blockIdx.x*64, n0 = blockIdx.y*64;
    int tid = threadIdx.x;
    int lane = tid & 31, w = tid >> 5;
    int wm = w >> 2, wn = w & 3;
    int rq = lane >> 2, rr = lane & 3;
    int la_m = tid >> 2, la_k = (tid & 3) << 2;
    int lb_k = tid >> 4, lb_n = (tid & 15) << 2;

    float acc[2][2][4];
#pragma unroll
    for (int i=0;i<2;i++)
#pragma unroll
        for (int j=0;j<2;j++)
#pragma unroll
            for (int c=0;c<4;c++) acc[i][j][c]=0.f;

    int m = m0 + la_m;
    const float* arow = x + ((size_t)(m/3)*4 + 1 + (m%3))*256;

    for (int k0=0;k0<256;k0+=16) {
        float4 av = *(const float4*)(arow + k0 + la_k);
        As[la_m*AST + la_k+0]=f2tf32(av.x); As[la_m*AST + la_k+1]=f2tf32(av.y);
        As[la_m*AST + la_k+2]=f2tf32(av.z); As[la_m*AST + la_k+3]=f2tf32(av.w);
        float4 bv4 = *(const float4*)(Wvec + (size_t)(k0+lb_k)*512 + n0 + lb_n);
        Bs[lb_k*BST + lb_n+0]=f2tf32(bv4.x); Bs[lb_k*BST + lb_n+1]=f2tf32(bv4.y);
        Bs[lb_k*BST + lb_n+2]=f2tf32(bv4.z); Bs[lb_k*BST + lb_n+3]=f2tf32(bv4.w);
        __syncthreads();
#pragma unroll
        for (int ks=0;ks<16;ks+=8) {
            uint32_t a[2][4], b[2][2];
#pragma unroll
            for (int mi=0;mi<2;mi++) {
                int rb = wm*32 + mi*16 + rq;
                a[mi][0] = As[(rb  )*AST + ks + rr];
                a[mi][1] = As[(rb+8)*AST + ks + rr];
                a[mi][2] = As[(rb  )*AST + ks + 4 + rr];
                a[mi][3] = As[(rb+8)*AST + ks + 4 + rr];
            }
#pragma unroll
            for (int ni=0;ni<2;ni++) {
                int cb = wn*16 + ni*8 + rq;
                b[ni][0] = Bs[(ks   + rr)*BST + cb];
                b[ni][1] = Bs[(ks+4 + rr)*BST + cb];
            }
#pragma unroll
            for (int mi=0;mi<2;mi++)
#pragma unroll
                for (int ni=0;ni<2;ni++) mma_tf32(acc[mi][ni], a[mi], b[ni]);
        }
        __syncthreads();
    }
#pragma unroll
    for (int mi=0;mi<2;mi++) {
#pragma unroll
        for (int ni=0;ni<2;ni++) {
            int col = n0 + wn*16 + ni*8 + 2*rr;
#pragma unroll
            for (int half=0; half<2; half++) {
                int mm = m0 + wm*32 + mi*16 + rq + half*8;
                float2 o = make_float2(acc[mi][ni][half*2+0], acc[mi][ni][half*2+1]);
                *(float2*)&g_vp[(size_t)mm*512 + col] = o;
            }
        }
    }
}

// ============== elementwise: vec_dot and vec_norm (per bn, j) =================
__global__ void vecdot_norm_kernel(const float* __restrict__ x)
{
    int bn = blockIdx.x, j = threadIdx.x;
    float vd = 0.f, s = 0.f;
#pragma unroll
    for (int c=0;c<3;c++) {
        float a  = g_vp[((size_t)bn*3 + c)*512 + j];
        float b2 = g_vp[((size_t)bn*3 + c)*512 + 256 + j];
        vd += a*b2;
        float xv = x[((size_t)bn*4 + 1 + c)*256 + j];
        s += xv*xv;
    }
    g_vd[(size_t)bn*256 + j] = vd;
    g_vn[(size_t)bn*256 + j] = sqrtf(s);
}

// ============== sliding-window attention (tensor-core tf32, 512 thr) ==========
// Block: (t, bh), 512 threads, 16 warps (wm 4 x wn 4). Each warp: 16 rows x 32 cols.
// Phase 1: S = Q.K^T via mma, band-skipped blocks.
// Phase 2: banded softmax (8 lanes/query, exact fp32; attn_out pre-rounding).
// Phase 3: O = W.VAL via mma, k-steps limited to the band of the 16-row block.
#define TQ 64
#define RS 128
#define WSTR 132      // wts stride (%32==4 -> conflict-free A pattern)
#define QST  36       // qs stride  (%32==4)
#define KTS  136      // ksT stride (%32==8 -> conflict-free B pattern)
#define VST  136      // val stride (%32==8)
#define SM_WTS 0                  // 64*132  = 8448
#define SM_QS  8448               // 64*36   = 2304
#define SM_KST (8448+2304)        // 32*136  = 4352  (end 15104)
#define SM_VAL 8448               // 128*136 = 17408 (overlaps qs+ksT after P1)
#define SM_TOTAL_F (8448+17408)   // 25856 floats = 103424 B

__global__ __launch_bounds__(512) void attn_kernel(
    const float* __restrict__ x, float* __restrict__ attn_out)
{
    extern __shared__ float sm[];
    float* wts = sm + SM_WTS;
    float* qs  = sm + SM_QS;
    float* ksT = sm + SM_KST;
    float* val = sm + SM_VAL;

    int t  = blockIdx.x;
    int bh = blockIdx.y;
    int b = bh >> 3, h = bh & 7;
    int n_base = t*TQ;
    int tid = threadIdx.x;
    int lane = tid & 31, w = tid >> 5;
    int wm = w >> 2, wn = w & 3;      // wm: 16-row block; wn: 32-col block
    int rq = lane >> 2, rr = lane & 3;

    // ---- stage K^T (tf32, transposed scatter) and Q (tf32, float4 loads) ----
    for (int idx = tid; idx < RS*8; idx += 512) {
        int r = idx >> 3, d4 = (idx & 7) << 2;
        int ng = n_base - WIN + r;
        float4 kv = make_float4(0.f,0.f,0.f,0.f);
        if (ng >= 0 && ng < NN)
            kv = *(const float4*)&g_k[((size_t)bh*NN + ng)*HD + d4];
        ksT[(d4+0)*KTS + r] = f2tf32f(kv.x);
        ksT[(d4+1)*KTS + r] = f2tf32f(kv.y);
        ksT[(d4+2)*KTS + r] = f2tf32f(kv.z);
        ksT[(d4+3)*KTS + r] = f2tf32f(kv.w);
    }
    for (int idx = tid; idx < TQ*8; idx += 512) {
        int qi = idx >> 3, d4 = (idx & 7) << 2;
        float4 qv = *(const float4*)&g_q[((size_t)bh*NN + n_base + qi)*HD + d4];
        qs[qi*QST + d4+0] = f2tf32f(qv.x);
        qs[qi*QST + d4+1] = f2tf32f(qv.y);
        qs[qi*QST + d4+2] = f2tf32f(qv.z);
        qs[qi*QST + d4+3] = f2tf32f(qv.w);
    }
    __syncthreads();

    // ---- phase 1: scores via mma (rows wm*16..+15, cols wn*32..+31) ----
    {
        // band for this row block: [wm*16, wm*16+79]; skip cols outside
        bool active = (wn*32 + 31 >= wm*16) && (wn*32 <= wm*16 + 79);
        if (active) {
            float acc[4][4];
#pragma unroll
            for (int j=0;j<4;j++)
#pragma unroll
                for (int c=0;c<4;c++) acc[j][c]=0.f;

#pragma unroll
            for (int ks=0;ks<32;ks+=8) {
                uint32_t a[4], bfr[4][2];
                int rb = wm*16 + rq;
                a[0] = ((const uint32_t*)qs)[(rb  )*QST + ks + rr];
                a[1] = ((const uint32_t*)qs)[(rb+8)*QST + ks + rr];
                a[2] = ((const uint32_t*)qs)[(rb  )*QST + ks + 4 + rr];
                a[3] = ((const uint32_t*)qs)[(rb+8)*QST + ks + 4 + rr];
#pragma unroll
                for (int ni=0;ni<4;ni++) {
                    int cb = wn*32 + ni*8 + rq;
                    bfr[ni][0] = ((const uint32_t*)ksT)[(ks   + rr)*KTS + cb];
                    bfr[ni][1] = ((const uint32_t*)ksT)[(ks+4 + rr)*KTS + cb];
                }
#pragma unroll
                for (int ni=0;ni<4;ni++) mma_tf32(acc[ni], a, bfr[ni]);
            }
            const float scale = 0.17677669529663687f;   // 1/sqrt(32)
#pragma unroll
            for (int ni=0;ni<4;ni++) {
                int col = wn*32 + ni*8 + 2*rr;
#pragma unroll
                for (int half=0; half<2; half++) {
                    int row = wm*16 + rq + half*8;
                    float2 o = make_float2(acc[ni][half*2+0]*scale,
                                           acc[ni][half*2+1]*scale);
                    *(float2*)&wts[row*WSTR + col] = o;
                }
            }
        }
    }
    __syncthreads();

    // ---- stage VAL (tf32, float4) — overwrites qs/ksT ----
    for (int idx = tid; idx < RS*32; idx += 512) {
        int r = idx >> 5, n4 = (idx & 31) << 2;
        int ng = n_base - WIN + r;
        float4 vv = make_float4(0.f,0.f,0.f,0.f);
        if (ng >= 0 && ng < NN) {
            if (n4 < 32) vv = *(const float4*)&g_v[((size_t)bh*NN + ng)*HD + n4];
            else {
                int c = (n4-32) >> 5, dd = (n4-32) & 31;
                vv = *(const float4*)&x[(((size_t)b*NN + ng)*4 + 1 + c)*256 + h*HD + dd];
            }
        }
        val[r*VST + n4+0] = f2tf32f(vv.x);
        val[r*VST + n4+1] = f2tf32f(vv.y);
        val[r*VST + n4+2] = f2tf32f(vv.z);
        val[r*VST + n4+3] = f2tf32f(vv.w);
    }

    // ---- phase 2: banded softmax (8 lanes per query) ----
    {
        int qi = tid >> 3, p = tid & 7;
        float* row = wts + qi*WSTR;
        float mx = -1e30f;
        for (int w2=p; w2<WLEN; w2+=8) mx = fmaxf(mx, row[qi + w2]);
        mx = fmaxf(mx, __shfl_xor_sync(0xffffffffu, mx, 1));
        mx = fmaxf(mx, __shfl_xor_sync(0xffffffffu, mx, 2));
        mx = fmaxf(mx, __shfl_xor_sync(0xffffffffu, mx, 4));
        float sum = 0.f;
        for (int w2=p; w2<WLEN; w2+=8) {
            float e = __expf(row[qi + w2] - mx);
            row[qi + w2] = e;
            sum += e;
        }
        sum += __shfl_xor_sync(0xffffffffu, sum, 1);
        sum += __shfl_xor_sync(0xffffffffu, sum, 2);
        sum += __shfl_xor_sync(0xffffffffu, sum, 4);
        float inv = 1.f/sum;
        float* ao = attn_out + ((size_t)bh*NN + n_base + qi)*WLEN;
        for (int w2=p; w2<WLEN; w2+=8) {
            float v = row[qi + w2]*inv;
            ao[w2] = v;                           // exact fp32 out
            row[qi + w2] = f2tf32f(v);            // rounded for mma
        }
        for (int r=p; r<RS; r+=8)
            if (r < qi || r > qi + WLEN - 1) row[r] = 0.f;
    }
    __syncthreads();

    // ---- phase 3: aggregation via mma, band-limited k-steps ----
    {
        float acc[4][4];
#pragma unroll
        for (int j=0;j<4;j++)
#pragma unroll
            for (int c=0;c<4;c++) acc[j][c]=0.f;

        // rows wm*16..+15 have weight support r in [wm*16, wm*16+79]
        int ks_lo = wm*16;
        int ks_hi = wm*16 + 79;    // inclusive; 10 k-steps of 8
        for (int ks=ks_lo; ks<=ks_hi; ks+=8) {
            uint32_t a[4], bfr[4][2];
            int rb = wm*16 + rq;
            a[0] = ((const uint32_t*)wts)[(rb  )*WSTR + ks + rr];
            a[1] = ((const uint32_t*)wts)[(rb+8)*WSTR + ks + rr];
            a[2] = ((const uint32_t*)wts)[(rb  )*WSTR + ks + 4 + rr];
            a[3] = ((const uint32_t*)wts)[(rb+8)*WSTR + ks + 4 + rr];
#pragma unroll
            for (int ni=0;ni<4;ni++) {
                int cb = wn*32 + ni*8 + rq;
                bfr[ni][0] = ((const uint32_t*)val)[(ks   + rr)*VST + cb];
                bfr[ni][1] = ((const uint32_t*)val)[(ks+4 + rr)*VST + cb];
            }
#pragma unroll
            for (int ni=0;ni<4;ni++) mma_tf32(acc[ni], a, bfr[ni]);
        }

        // epilogue: wn==0 -> g_xout (dims 0..31); wn>=1 -> g_vaggr channel wn-1
#pragma unroll
        for (int ni=0;ni<4;ni++) {
            int dd = ni*8 + 2*rr;
#pragma unroll
            for (int half=0; half<2; half++) {
                int qrow = wm*16 + rq + half*8;
                int n = n_base + qrow;
                float2 o = make_float2(acc[ni][half*2+0], acc[ni][half*2+1]);
                if (wn == 0)
                    *(float2*)&g_xout[((size_t)b*NN + n)*HH + h*HD + dd] = o;
                else
                    *(float2*)&g_vaggr[(((size_t)b*NN + n)*3 + (wn-1))*HH + h*HD + dd] = o;
            }
        }
    }
}

// ============ tf32 GEMM: gate (M=4096,N=256,K=512) + sigmoid ==================
__global__ __launch_bounds__(256) void gemm_gate_kernel(
    const float* __restrict__ p_ad, const float* __restrict__ p_an,
    const float* __restrict__ Wg, const float* __restrict__ bg)
{
    __shared__ uint32_t As[64*AST];
    __shared__ uint32_t Bs[16*BST];
    float ad = *p_ad, an = *p_an;
    int m0 = blockIdx.x*64, n0 = blockIdx.y*64;
    int tid = threadIdx.x;
    int lane = tid & 31, w = tid >> 5;
    int wm = w >> 2, wn = w & 3;
    int rq = lane >> 2, rr = lane & 3;
    int la_m = tid >> 2, la_k = (tid & 3) << 2;
    int lb_k = tid >> 4, lb_n = (tid & 15) << 2;

    float acc[2][2][4];
#pragma unroll
    for (int i=0;i<2;i++)
#pragma unroll
        for (int j=0;j<2;j++)
#pragma unroll
            for (int c=0;c<4;c++) acc[i][j][c]=0.f;

    int m = m0 + la_m;
    for (int k0=0;k0<512;k0+=16) {
        int i0 = k0 + la_k;
        float4 av;
        if (i0 < 256) {
            av = *(const float4*)(g_vd + (size_t)m*256 + i0);
            av.x*=ad; av.y*=ad; av.z*=ad; av.w*=ad;
        } else {
            av = *(const float4*)(g_vn + (size_t)m*256 + i0 - 256);
            av.x*=an; av.y*=an; av.z*=an; av.w*=an;
        }
        As[la_m*AST + la_k+0]=f2tf32(av.x); As[la_m*AST + la_k+1]=f2tf32(av.y);
        As[la_m*AST + la_k+2]=f2tf32(av.z); As[la_m*AST + la_k+3]=f2tf32(av.w);
        float4 bv4 = *(const float4*)(Wg + (size_t)(k0+lb_k)*256 + n0 + lb_n);
        Bs[lb_k*BST + lb_n+0]=f2tf32(bv4.x); Bs[lb_k*BST + lb_n+1]=f2tf32(bv4.y);
        Bs[lb_k*BST + lb_n+2]=f2tf32(bv4.z); Bs[lb_k*BST + lb_n+3]=f2tf32(bv4.w);
        __syncthreads();
#pragma unroll
        for (int ks=0;ks<16;ks+=8) {
            uint32_t a[2][4], b[2][2];
#pragma unroll
            for (int mi=0;mi<2;mi++) {
                int rb = wm*32 + mi*16 + rq;
                a[mi][0] = As[(rb  )*AST + ks + rr];
                a[mi][1] = As[(rb+8)*AST + ks + rr];
                a[mi][2] = As[(rb  )*AST + ks + 4 + rr];
                a[mi][3] = As[(rb+8)*AST + ks + 4 + rr];
            }
#pragma unroll
            for (int ni=0;ni<2;ni++) {
                int cb = wn*16 + ni*8 + rq;
                b[ni][0] = Bs[(ks   + rr)*BST + cb];
                b[ni][1] = Bs[(ks+4 + rr)*BST + cb];
            }
#pragma unroll
            for (int mi=0;mi<2;mi++)
#pragma unroll
                for (int ni=0;ni<2;ni++) mma_tf32(acc[mi][ni], a[mi], b[ni]);
        }
        __syncthreads();
    }
#pragma unroll
    for (int mi=0;mi<2;mi++) {
#pragma unroll
        for (int ni=0;ni<2;ni++) {
            int col = n0 + wn*16 + ni*8 + 2*rr;
            float b0 = bg[col], b1 = bg[col+1];
#pragma unroll
            for (int half=0; half<2; half++) {
                int mm = m0 + wm*32 + mi*16 + rq + half*8;
                float v0 = acc[mi][ni][half*2+0] + b0;
                float v1 = acc[mi][ni][half*2+1] + b1;
                float2 o = make_float2(1.f/(1.f + __expf(-v0)), 1.f/(1.f + __expf(-v1)));
                *(float2*)&g_gate[(size_t)mm*256 + col] = o;
            }
        }
    }
}

// ============ tf32 GEMM: out-proj (M=4096,N=768,K=256) -> g_o =================
__global__ __launch_bounds__(256) void gemm_final_kernel(const float* __restrict__ Wo)
{
    __shared__ uint32_t As[64*AST];
    __shared__ uint32_t Bs[16*BST];
    int m0 = blockIdx.x*64, n0 = blockIdx.y*64;
    int tid = threadIdx.x;
    int lane = tid & 31, w = tid >> 5;
    int wm = w >> 2, wn = w & 3;
    int rq = lane >> 2, rr = lane & 3;
    int la_m = tid >> 2, la_k = (tid & 3) << 2;
    int lb_k = tid >> 4, lb_n = (tid & 15) << 2;

    float acc[2][2][4];
#pragma unroll
    for (int i=0;i<2;i++)
#pragma unroll
        for (int j=0;j<2;j++)
#pragma unroll
            for (int c=0;c<4;c++) acc[i][j][c]=0.f;

    for (int k0=0;k0<256;k0+=16) {
        float4 av = *(const float4*)(g_xout + (size_t)(m0+la_m)*256 + k0 + la_k);
        As[la_m*AST + la_k+0]=f2tf32(av.x); As[la_m*AST + la_k+1]=f2tf32(av.y);
        As[la_m*AST + la_k+2]=f2tf32(av.z); As[la_m*AST + la_k+3]=f2tf32(av.w);
        float4 bv4 = *(const float4*)(Wo + (size_t)(k0+lb_k)*768 + n0 + lb_n);
        Bs[lb_k*BST + lb_n+0]=f2tf32(bv4.x); Bs[lb_k*BST + lb_n+1]=f2tf32(bv4.y);
        Bs[lb_k*BST + lb_n+2]=f2tf32(bv4.z); Bs[lb_k*BST + lb_n+3]=f2tf32(bv4.w);
        __syncthreads();
#pragma unroll
        for (int ks=0;ks<16;ks+=8) {
            uint32_t a[2][4], b[2][2];
#pragma unroll
            for (int mi=0;mi<2;mi++) {
                int rb = wm*32 + mi*16 + rq;
                a[mi][0] = As[(rb  )*AST + ks + rr];
                a[mi][1] = As[(rb+8)*AST + ks + rr];
                a[mi][2] = As[(rb  )*AST + ks + 4 + rr];
                a[mi][3] = As[(rb+8)*AST + ks + 4 + rr];
            }
#pragma unroll
            for (int ni=0;ni<2;ni++) {
                int cb = wn*16 + ni*8 + rq;
                b[ni][0] = Bs[(ks   + rr)*BST + cb];
                b[ni][1] = Bs[(ks+4 + rr)*BST + cb];
            }
#pragma unroll
            for (int mi=0;mi<2;mi++)
#pragma unroll
                for (int ni=0;ni<2;ni++) mma_tf32(acc[mi][ni], a[mi], b[ni]);
        }
        __syncthreads();
    }
#pragma unroll
    for (int mi=0;mi<2;mi++) {
#pragma unroll
        for (int ni=0;ni<2;ni++) {
            int col = n0 + wn*16 + ni*8 + 2*rr;
#pragma unroll
            for (int half=0; half<2; half++) {
                int mm = m0 + wm*32 + mi*16 + rq + half*8;
                float2 o = make_float2(acc[mi][ni][half*2+0], acc[mi][ni][half*2+1]);
                *(float2*)&g_o[(size_t)mm*768 + col] = o;
            }
        }
    }
}

// ====== epilogue: all 4 output channels (finalize + combine merged) ===========
__global__ void epilogue_kernel(const float* __restrict__ x,
                                const float* __restrict__ bo, float* __restrict__ out)
{
    int idx = blockIdx.x*blockDim.x + threadIdx.x;
    if (idx >= BN*1024) return;
    int j  = idx & 255;
    int ch = (idx >> 8) & 3;
    int m  = idx >> 10;
    if (ch == 0) {
        float o1 = g_o[(size_t)m*768 + j]       + bo[j];
        float o2 = g_o[(size_t)m*768 + 256 + j] + bo[256 + j];
        float o3 = g_o[(size_t)m*768 + 512 + j] + bo[512 + j];
        float vd = g_vd[(size_t)m*256 + j];
        float vn = g_vn[(size_t)m*256 + j];
        out[idx] = vd*o1 + vn*o2 + o3;
    } else {
        int c = ch - 1;
        float g  = g_gate[(size_t)m*256 + j];
        float va = g_vaggr[((size_t)m*3 + c)*256 + j];
        out[idx] = g*va + x[idx];
    }
}

// ================================ launch ======================================
extern "C" void kernel_launch(void* const* d_in, const int* in_sizes, int n_in,
                              void* d_out, int out_size)
{
    const float* x    = (const float*)d_in[0];
    const float* Wq   = (const float*)d_in[1];
    const float* bq   = (const float*)d_in[2];
    const float* Wk   = (const float*)d_in[3];
    const float* bk   = (const float*)d_in[4];
    const float* Wv   = (const float*)d_in[5];
    const float* bv   = (const float*)d_in[6];
    const float* Wo   = (const float*)d_in[7];
    const float* bo   = (const float*)d_in[8];
    const float* Wvec = (const float*)d_in[9];
    const float* p_ad = (const float*)d_in[10];
    const float* p_an = (const float*)d_in[11];
    const float* Wg   = (const float*)d_in[12];
    const float* bg   = (const float*)d_in[13];

    float* out = (float*)d_out;
    float* attn_out = out + (size_t)BN*4*256;   // x_final first, then attn_weights

    const int attn_smem = SM_TOTAL_F * 4;       // 103,424 B
    cudaFuncSetAttribute(attn_kernel, cudaFuncAttributeMaxDynamicSharedMemorySize, attn_smem);

    gemm_qkv_kernel<<<dim3(64,4,3), 256>>>(x, Wq, Wk, Wv, bq, bk, bv);
    gemm_vp_kernel<<<dim3(192,8), 256>>>(x, Wvec);
    vecdot_norm_kernel<<<BN, 256>>>(x);
    attn_kernel<<<dim3(NN/TQ,16), 512, attn_smem>>>(x, attn_out);
    gemm_gate_kernel<<<dim3(64,4), 256>>>(p_ad, p_an, Wg, bg);
    gemm_final_kernel<<<dim3(64,12), 256>>>(Wo);
    epilogue_kernel<<<(BN*1024 + 255)/256, 256>>>(x, bo, out);
}

// round 17
// speedup vs baseline: 3.0273x; 1.2015x over previous
#include <cuda_runtime.h>
#include <cuda_bf16.h>
#include <math.h>
#include <stdint.h>

// Problem constants
// B=2, N=2048, H=256, heads=8, d=32, WIN=32, WIN_LEN=65
#define BB 2
#define NN 2048
#define HH 256
#define NH 8
#define HD 32
#define WIN 32
#define WLEN 65
#define BHN (BB*NH)         // 16
#define BN (BB*NN)          // 4096

// ---------------- scratch (device globals; no allocation allowed) -------------
__device__ float g_q[BHN*NN*HD];        // (bh, n, d)
__device__ float g_k[BHN*NN*HD];
__device__ float g_v[BHN*NN*HD];
__device__ float g_vp[BN*3*512];        // vec_proj (bn*3+c, 512)
__device__ float g_vd[BN*HH];           // vec_dot (bn, j)
__device__ float g_vn[BN*HH];           // vec_norm
__device__ float g_vdn[BN*512];         // [ad*vd | an*vn] contiguous (gate A)
__device__ float g_xout[BN*HH];         // x_out (bn, H)
__device__ float g_vaggr[BN*3*HH];      // (bn, c, H)
__device__ float g_gate[BN*HH];
__device__ float g_o[BN*768];           // out-proj scratch (m, 768)

// ========================= tf32 mma helpers ==================================
__device__ __forceinline__ uint32_t f2tf32(float f) {
    uint32_t r;
    asm("cvt.rna.tf32.f32 %0, %1;" : "=r"(r) : "f"(f));
    return r;
}
__device__ __forceinline__ float f2tf32f(float f) {
    return __uint_as_float(f2tf32(f));
}

__device__ __forceinline__ void mma_tf32(float* c, const uint32_t* a, const uint32_t* b) {
    asm volatile(
        "mma.sync.aligned.m16n8k8.row.col.f32.tf32.tf32.f32 "
        "{%0,%1,%2,%3}, {%4,%5,%6,%7}, {%8,%9}, {%0,%1,%2,%3};\n"
        : "+f"(c[0]), "+f"(c[1]), "+f"(c[2]), "+f"(c[3])
        : "r"(a[0]), "r"(a[1]), "r"(a[2]), "r"(a[3]), "r"(b[0]), "r"(b[1]));
}

__device__ __forceinline__ void cp16(uint32_t smem, const void* gmem) {
    asm volatile("cp.async.ca.shared.global [%0], [%1], 16;\n" :: "r"(smem), "l"(gmem));
}
#define CP_COMMIT() asm volatile("cp.async.commit_group;\n" ::: "memory")
#define CP_WAIT(n)  asm volatile("cp.async.wait_group %0;\n" :: "n"(n) : "memory")

// -------- pipelined 128x128 tf32 GEMM core (shared by 4 kernels) --------------
// CTA: 256 threads, 8 warps (wm 2 x wn 4). Warp tile 64x32 (mi 4 x ni 4).
// k-chunk 16, double-buffered cp.async staging, raw fp32 bits as tf32 (trunc).
#define GAST 20     // A smem stride (words), %32==4 -> conflict-free
#define GBST 136    // B smem stride (words), %32==8 -> conflict-free
#define ABUF (128*GAST)   // 2560
#define BBUF (16*GBST)    // 2176

// staging geometry (per thread): A granules at rows tA>>2 and +64, seg (tA&3)*4
//                                B granules at rows tid>>5 and +8,  seg (tid&31)*4

#define GEMM_PIPE_BODY(A_ROW_PTR, LDB, KDIM, BPTR)                              \
    __shared__ uint32_t As[2*ABUF];                                             \
    __shared__ uint32_t Bs[2*BBUF];                                             \
    int tid = threadIdx.x;                                                      \
    int lane = tid & 31, w = tid >> 5;                                          \
    int wm = w >> 2, wn = w & 3;                                                \
    int rq = lane >> 2, rr = lane & 3;                                          \
    int rowA = tid >> 2, segA = (tid & 3) << 2;                                 \
    int rowB = tid >> 5, segB = (tid & 31) << 2;                                \
    const float* aPtr0 = A_ROW_PTR(rowA) + segA;                                \
    const float* aPtr1 = A_ROW_PTR(rowA + 64) + segA;                           \
    const float* bPtr0 = (BPTR) + (size_t)rowB*(LDB) + n0 + segB;               \
    const float* bPtr1 = (BPTR) + (size_t)(rowB+8)*(LDB) + n0 + segB;           \
    uint32_t sAb = (uint32_t)__cvta_generic_to_shared(As);                      \
    uint32_t sBb = (uint32_t)__cvta_generic_to_shared(Bs);                      \
    uint32_t sA0 = sAb + ((rowA*GAST + segA) << 2);                             \
    uint32_t sA1 = sAb + (((rowA+64)*GAST + segA) << 2);                        \
    uint32_t sB0 = sBb + ((rowB*GBST + segB) << 2);                             \
    uint32_t sB1 = sBb + (((rowB+8)*GBST + segB) << 2);                         \
    float acc[4][4][4];                                                         \
    _Pragma("unroll")                                                           \
    for (int i=0;i<4;i++) _Pragma("unroll")                                     \
        for (int j=0;j<4;j++) _Pragma("unroll")                                 \
            for (int c=0;c<4;c++) acc[i][j][c]=0.f;                             \
    /* prologue: stage k0=0 into buf0 */                                        \
    cp16(sA0, aPtr0); cp16(sA1, aPtr1);                                         \
    cp16(sB0, bPtr0); cp16(sB1, bPtr1);                                         \
    CP_COMMIT();                                                                \
    int buf = 0;                                                                \
    for (int k0=0; k0<(KDIM); k0+=16) {                                         \
        bool has_next = (k0+16) < (KDIM);                                       \
        if (has_next) {                                                         \
            int nb = buf^1;                                                     \
            cp16(sA0 + nb*(ABUF<<2), aPtr0 + k0+16);                            \
            cp16(sA1 + nb*(ABUF<<2), aPtr1 + k0+16);                            \
            cp16(sB0 + nb*(BBUF<<2), bPtr0 + (size_t)(k0+16)*(LDB));            \
            cp16(sB1 + nb*(BBUF<<2), bPtr1 + (size_t)(k0+16)*(LDB));            \
            CP_COMMIT();                                                        \
            CP_WAIT(1);                                                         \
        } else {                                                                \
            CP_WAIT(0);                                                         \
        }                                                                       \
        __syncthreads();                                                        \
        const uint32_t* Ab = As + buf*ABUF;                                     \
        const uint32_t* Bb = Bs + buf*BBUF;                                     \
        _Pragma("unroll")                                                       \
        for (int ks=0;ks<16;ks+=8) {                                            \
            uint32_t afr[4][4], bfr[4][2];                                      \
            _Pragma("unroll")                                                   \
            for (int mi=0;mi<4;mi++) {                                          \
                int rb = wm*64 + mi*16 + rq;                                    \
                afr[mi][0] = Ab[(rb  )*GAST + ks + rr];                         \
                afr[mi][1] = Ab[(rb+8)*GAST + ks + rr];                         \
                afr[mi][2] = Ab[(rb  )*GAST + ks + 4 + rr];                     \
                afr[mi][3] = Ab[(rb+8)*GAST + ks + 4 + rr];                     \
            }                                                                   \
            _Pragma("unroll")                                                   \
            for (int ni=0;ni<4;ni++) {                                          \
                int cb = wn*32 + ni*8 + rq;                                     \
                bfr[ni][0] = Bb[(ks   + rr)*GBST + cb];                         \
                bfr[ni][1] = Bb[(ks+4 + rr)*GBST + cb];                         \
            }                                                                   \
            _Pragma("unroll")                                                   \
            for (int mi=0;mi<4;mi++) _Pragma("unroll")                          \
                for (int ni=0;ni<4;ni++) mma_tf32(acc[mi][ni], afr[mi], bfr[ni]);\
        }                                                                       \
        __syncthreads();                                                        \
        buf ^= 1;                                                               \
    }

// ======================= tf32 GEMM: QKV (M=4096,N=256,K=256) ==================
#define QKV_AROW(r) (x + (size_t)(m0 + (r))*1024)
__global__ __launch_bounds__(256) void gemm_qkv_kernel(
    const float* __restrict__ x,
    const float* __restrict__ Wq, const float* __restrict__ Wk, const float* __restrict__ Wv,
    const float* __restrict__ bq, const float* __restrict__ bk, const float* __restrict__ bv)
{
    int z = blockIdx.z;
    const float* W    = (z==0) ? Wq : (z==1 ? Wk : Wv);
    const float* bias = (z==0) ? bq : (z==1 ? bk : bv);
    float* dst        = (z==0) ? g_q : (z==1 ? g_k : g_v);
    int m0 = blockIdx.x*128, n0 = blockIdx.y*128;

    GEMM_PIPE_BODY(QKV_AROW, 256, 256, W)

#pragma unroll
    for (int mi=0;mi<4;mi++) {
#pragma unroll
        for (int ni=0;ni<4;ni++) {
            int col = n0 + wn*32 + ni*8 + 2*rr;
            int h = col >> 5, dd = col & 31;
            float b0 = bias[col], b1 = bias[col+1];
#pragma unroll
            for (int half=0; half<2; half++) {
                int m = m0 + wm*64 + mi*16 + rq + half*8;
                int bb = m >> 11, n = m & 2047;
                float2 o = make_float2(acc[mi][ni][half*2+0] + b0,
                                       acc[mi][ni][half*2+1] + b1);
                *(float2*)&dst[(((size_t)(bb*NH + h))*NN + n)*HD + dd] = o;
            }
        }
    }
}

// =================== tf32 GEMM: vec_proj (M=12288,N=512,K=256) ================
#define VP_AROW(r) (x + ((size_t)((m0 + (r))/3)*4 + 1 + (m0 + (r))%3)*256)
__global__ __launch_bounds__(256) void gemm_vp_kernel(
    const float* __restrict__ x, const float* __restrict__ Wvec)
{
    int m0 = blockIdx.x*128, n0 = blockIdx.y*128;

    GEMM_PIPE_BODY(VP_AROW, 512, 256, Wvec)

#pragma unroll
    for (int mi=0;mi<4;mi++) {
#pragma unroll
        for (int ni=0;ni<4;ni++) {
            int col = n0 + wn*32 + ni*8 + 2*rr;
#pragma unroll
            for (int half=0; half<2; half++) {
                int mm = m0 + wm*64 + mi*16 + rq + half*8;
                float2 o = make_float2(acc[mi][ni][half*2+0], acc[mi][ni][half*2+1]);
                *(float2*)&g_vp[(size_t)mm*512 + col] = o;
            }
        }
    }
}

// ============== elementwise: vec_dot, vec_norm, scaled concat =================
__global__ void vecdot_norm_kernel(const float* __restrict__ x,
                                   const float* __restrict__ p_ad,
                                   const float* __restrict__ p_an)
{
    int bn = blockIdx.x, j = threadIdx.x;
    float ad = *p_ad, an = *p_an;
    float vd = 0.f, s = 0.f;
#pragma unroll
    for (int c=0;c<3;c++) {
        float a  = g_vp[((size_t)bn*3 + c)*512 + j];
        float b2 = g_vp[((size_t)bn*3 + c)*512 + 256 + j];
        vd += a*b2;
        float xv = x[((size_t)bn*4 + 1 + c)*256 + j];
        s += xv*xv;
    }
    float vn = sqrtf(s);
    g_vd[(size_t)bn*256 + j] = vd;
    g_vn[(size_t)bn*256 + j] = vn;
    g_vdn[(size_t)bn*512 + j]       = ad*vd;
    g_vdn[(size_t)bn*512 + 256 + j] = an*vn;
}

// ============== sliding-window attention (tensor-core tf32, 512 thr) ==========
#define TQ 64
#define RS 128
#define WSTR 132
#define QST  36
#define KTS  136
#define VST  136
#define SM_WTS 0
#define SM_QS  8448
#define SM_KST (8448+2304)
#define SM_VAL 8448
#define SM_TOTAL_F (8448+17408)   // 25856 floats = 103424 B

__global__ __launch_bounds__(512) void attn_kernel(
    const float* __restrict__ x, float* __restrict__ attn_out)
{
    extern __shared__ float sm[];
    float* wts = sm + SM_WTS;
    float* qs  = sm + SM_QS;
    float* ksT = sm + SM_KST;
    float* val = sm + SM_VAL;

    int t  = blockIdx.x;
    int bh = blockIdx.y;
    int b = bh >> 3, h = bh & 7;
    int n_base = t*TQ;
    int tid = threadIdx.x;
    int lane = tid & 31, w = tid >> 5;
    int wm = w >> 2, wn = w & 3;
    int rq = lane >> 2, rr = lane & 3;

    for (int idx = tid; idx < RS*8; idx += 512) {
        int r = idx >> 3, d4 = (idx & 7) << 2;
        int ng = n_base - WIN + r;
        float4 kv = make_float4(0.f,0.f,0.f,0.f);
        if (ng >= 0 && ng < NN)
            kv = *(const float4*)&g_k[((size_t)bh*NN + ng)*HD + d4];
        ksT[(d4+0)*KTS + r] = f2tf32f(kv.x);
        ksT[(d4+1)*KTS + r] = f2tf32f(kv.y);
        ksT[(d4+2)*KTS + r] = f2tf32f(kv.z);
        ksT[(d4+3)*KTS + r] = f2tf32f(kv.w);
    }
    for (int idx = tid; idx < TQ*8; idx += 512) {
        int qi = idx >> 3, d4 = (idx & 7) << 2;
        float4 qv = *(const float4*)&g_q[((size_t)bh*NN + n_base + qi)*HD + d4];
        qs[qi*QST + d4+0] = f2tf32f(qv.x);
        qs[qi*QST + d4+1] = f2tf32f(qv.y);
        qs[qi*QST + d4+2] = f2tf32f(qv.z);
        qs[qi*QST + d4+3] = f2tf32f(qv.w);
    }
    __syncthreads();

    {
        bool active = (wn*32 + 31 >= wm*16) && (wn*32 <= wm*16 + 79);
        if (active) {
            float acc[4][4];
#pragma unroll
            for (int j=0;j<4;j++)
#pragma unroll
                for (int c=0;c<4;c++) acc[j][c]=0.f;

#pragma unroll
            for (int ks=0;ks<32;ks+=8) {
                uint32_t a[4], bfr[4][2];
                int rb = wm*16 + rq;
                a[0] = ((const uint32_t*)qs)[(rb  )*QST + ks + rr];
                a[1] = ((const uint32_t*)qs)[(rb+8)*QST + ks + rr];
                a[2] = ((const uint32_t*)qs)[(rb  )*QST + ks + 4 + rr];
                a[3] = ((const uint32_t*)qs)[(rb+8)*QST + ks + 4 + rr];
#pragma unroll
                for (int ni=0;ni<4;ni++) {
                    int cb = wn*32 + ni*8 + rq;
                    bfr[ni][0] = ((const uint32_t*)ksT)[(ks   + rr)*KTS + cb];
                    bfr[ni][1] = ((const uint32_t*)ksT)[(ks+4 + rr)*KTS + cb];
                }
#pragma unroll
                for (int ni=0;ni<4;ni++) mma_tf32(acc[ni], a, bfr[ni]);
            }
            const float scale = 0.17677669529663687f;   // 1/sqrt(32)
#pragma unroll
            for (int ni=0;ni<4;ni++) {
                int col = wn*32 + ni*8 + 2*rr;
#pragma unroll
                for (int half=0; half<2; half++) {
                    int row = wm*16 + rq + half*8;
                    float2 o = make_float2(acc[ni][half*2+0]*scale,
                                           acc[ni][half*2+1]*scale);
                    *(float2*)&wts[row*WSTR + col] = o;
                }
            }
        }
    }
    __syncthreads();

    for (int idx = tid; idx < RS*32; idx += 512) {
        int r = idx >> 5, n4 = (idx & 31) << 2;
        int ng = n_base - WIN + r;
        float4 vv = make_float4(0.f,0.f,0.f,0.f);
        if (ng >= 0 && ng < NN) {
            if (n4 < 32) vv = *(const float4*)&g_v[((size_t)bh*NN + ng)*HD + n4];
            else {
                int c = (n4-32) >> 5, dd = (n4-32) & 31;
                vv = *(const float4*)&x[(((size_t)b*NN + ng)*4 + 1 + c)*256 + h*HD + dd];
            }
        }
        val[r*VST + n4+0] = f2tf32f(vv.x);
        val[r*VST + n4+1] = f2tf32f(vv.y);
        val[r*VST + n4+2] = f2tf32f(vv.z);
        val[r*VST + n4+3] = f2tf32f(vv.w);
    }

    {
        int qi = tid >> 3, p = tid & 7;
        float* row = wts + qi*WSTR;
        float mx = -1e30f;
        for (int w2=p; w2<WLEN; w2+=8) mx = fmaxf(mx, row[qi + w2]);
        mx = fmaxf(mx, __shfl_xor_sync(0xffffffffu, mx, 1));
        mx = fmaxf(mx, __shfl_xor_sync(0xffffffffu, mx, 2));
        mx = fmaxf(mx, __shfl_xor_sync(0xffffffffu, mx, 4));
        float sum = 0.f;
        for (int w2=p; w2<WLEN; w2+=8) {
            float e = __expf(row[qi + w2] - mx);
            row[qi + w2] = e;
            sum += e;
        }
        sum += __shfl_xor_sync(0xffffffffu, sum, 1);
        sum += __shfl_xor_sync(0xffffffffu, sum, 2);
        sum += __shfl_xor_sync(0xffffffffu, sum, 4);
        float inv = 1.f/sum;
        float* ao = attn_out + ((size_t)bh*NN + n_base + qi)*WLEN;
        for (int w2=p; w2<WLEN; w2+=8) {
            float v = row[qi + w2]*inv;
            ao[w2] = v;
            row[qi + w2] = f2tf32f(v);
        }
        for (int r=p; r<RS; r+=8)
            if (r < qi || r > qi + WLEN - 1) row[r] = 0.f;
    }
    __syncthreads();

    {
        float acc[4][4];
#pragma unroll
        for (int j=0;j<4;j++)
#pragma unroll
            for (int c=0;c<4;c++) acc[j][c]=0.f;

        int ks_lo = wm*16;
        int ks_hi = wm*16 + 79;
        for (int ks=ks_lo; ks<=ks_hi; ks+=8) {
            uint32_t a[4], bfr[4][2];
            int rb = wm*16 + rq;
            a[0] = ((const uint32_t*)wts)[(rb  )*WSTR + ks + rr];
            a[1] = ((const uint32_t*)wts)[(rb+8)*WSTR + ks + rr];
            a[2] = ((const uint32_t*)wts)[(rb  )*WSTR + ks + 4 + rr];
            a[3] = ((const uint32_t*)wts)[(rb+8)*WSTR + ks + 4 + rr];
#pragma unroll
            for (int ni=0;ni<4;ni++) {
                int cb = wn*32 + ni*8 + rq;
                bfr[ni][0] = ((const uint32_t*)val)[(ks   + rr)*VST + cb];
                bfr[ni][1] = ((const uint32_t*)val)[(ks+4 + rr)*VST + cb];
            }
#pragma unroll
            for (int ni=0;ni<4;ni++) mma_tf32(acc[ni], a, bfr[ni]);
        }

#pragma unroll
        for (int ni=0;ni<4;ni++) {
            int dd = ni*8 + 2*rr;
#pragma unroll
            for (int half=0; half<2; half++) {
                int qrow = wm*16 + rq + half*8;
                int n = n_base + qrow;
                float2 o = make_float2(acc[ni][half*2+0], acc[ni][half*2+1]);
                if (wn == 0)
                    *(float2*)&g_xout[((size_t)b*NN + n)*HH + h*HD + dd] = o;
                else
                    *(float2*)&g_vaggr[(((size_t)b*NN + n)*3 + (wn-1))*HH + h*HD + dd] = o;
            }
        }
    }
}

// ============ tf32 GEMM: gate (M=4096,N=256,K=512) + sigmoid ==================
#define GATE_AROW(r) (g_vdn + (size_t)(m0 + (r))*512)
__global__ __launch_bounds__(256) void gemm_gate_kernel(
    const float* __restrict__ Wg, const float* __restrict__ bg)
{
    int m0 = blockIdx.x*128, n0 = blockIdx.y*128;

    GEMM_PIPE_BODY(GATE_AROW, 256, 512, Wg)

#pragma unroll
    for (int mi=0;mi<4;mi++) {
#pragma unroll
        for (int ni=0;ni<4;ni++) {
            int col = n0 + wn*32 + ni*8 + 2*rr;
            float b0 = bg[col], b1 = bg[col+1];
#pragma unroll
            for (int half=0; half<2; half++) {
                int mm = m0 + wm*64 + mi*16 + rq + half*8;
                float v0 = acc[mi][ni][half*2+0] + b0;
                float v1 = acc[mi][ni][half*2+1] + b1;
                float2 o = make_float2(1.f/(1.f + __expf(-v0)), 1.f/(1.f + __expf(-v1)));
                *(float2*)&g_gate[(size_t)mm*256 + col] = o;
            }
        }
    }
}

// ============ tf32 GEMM: out-proj (M=4096,N=768,K=256) -> g_o =================
#define FIN_AROW(r) (g_xout + (size_t)(m0 + (r))*256)
__global__ __launch_bounds__(256) void gemm_final_kernel(const float* __restrict__ Wo)
{
    int m0 = blockIdx.x*128, n0 = blockIdx.y*128;

    GEMM_PIPE_BODY(FIN_AROW, 768, 256, Wo)

#pragma unroll
    for (int mi=0;mi<4;mi++) {
#pragma unroll
        for (int ni=0;ni<4;ni++) {
            int col = n0 + wn*32 + ni*8 + 2*rr;
#pragma unroll
            for (int half=0; half<2; half++) {
                int mm = m0 + wm*64 + mi*16 + rq + half*8;
                float2 o = make_float2(acc[mi][ni][half*2+0], acc[mi][ni][half*2+1]);
                *(float2*)&g_o[(size_t)mm*768 + col] = o;
            }
        }
    }
}

// ====== epilogue: all 4 output channels (finalize + combine merged) ===========
__global__ void epilogue_kernel(const float* __restrict__ x,
                                const float* __restrict__ bo, float* __restrict__ out)
{
    int idx = blockIdx.x*blockDim.x + threadIdx.x;
    if (idx >= BN*1024) return;
    int j  = idx & 255;
    int ch = (idx >> 8) & 3;
    int m  = idx >> 10;
    if (ch == 0) {
        float o1 = g_o[(size_t)m*768 + j]       + bo[j];
        float o2 = g_o[(size_t)m*768 + 256 + j] + bo[256 + j];
        float o3 = g_o[(size_t)m*768 + 512 + j] + bo[512 + j];
        float vd = g_vd[(size_t)m*256 + j];
        float vn = g_vn[(size_t)m*256 + j];
        out[idx] = vd*o1 + vn*o2 + o3;
    } else {
        int c = ch - 1;
        float g  = g_gate[(size_t)m*256 + j];
        float va = g_vaggr[((size_t)m*3 + c)*256 + j];
        out[idx] = g*va + x[idx];
    }
}

// ================================ launch ======================================
extern "C" void kernel_launch(void* const* d_in, const int* in_sizes, int n_in,
                              void* d_out, int out_size)
{
    const float* x    = (const float*)d_in[0];
    const float* Wq   = (const float*)d_in[1];
    const float* bq   = (const float*)d_in[2];
    const float* Wk   = (const float*)d_in[3];
    const float* bk   = (const float*)d_in[4];
    const float* Wv   = (const float*)d_in[5];
    const float* bv   = (const float*)d_in[6];
    const float* Wo   = (const float*)d_in[7];
    const float* bo   = (const float*)d_in[8];
    const float* Wvec = (const float*)d_in[9];
    const float* p_ad = (const float*)d_in[10];
    const float* p_an = (const float*)d_in[11];
    const float* Wg   = (const float*)d_in[12];
    const float* bg   = (const float*)d_in[13];

    float* out = (float*)d_out;
    float* attn_out = out + (size_t)BN*4*256;   // x_final first, then attn_weights

    const int attn_smem = SM_TOTAL_F * 4;       // 103,424 B
    cudaFuncSetAttribute(attn_kernel, cudaFuncAttributeMaxDynamicSharedMemorySize, attn_smem);

    gemm_qkv_kernel<<<dim3(32,2,3), 256>>>(x, Wq, Wk, Wv, bq, bk, bv);
    gemm_vp_kernel<<<dim3(96,4), 256>>>(x, Wvec);
    vecdot_norm_kernel<<<BN, 256>>>(x, p_ad, p_an);
    attn_kernel<<<dim3(NN/TQ,16), 512, attn_smem>>>(x, attn_out);
    gemm_gate_kernel<<<dim3(32,2), 256>>>(Wg, bg);
    gemm_final_kernel<<<dim3(32,6), 256>>>(Wo);
    epilogue_kernel<<<(BN*1024 + 255)/256, 256>>>(x, bo, out);
}